// round 2
// baseline (speedup 1.0000x reference)
#include <cuda_runtime.h>
#include <cstdint>

#define B_ 4
#define S_ 2048
#define E_ 1024
#define H_ 16
#define D_ 64
#define LN_EPS 1e-5f
#define LR 0.1f

// ---------------- scratch (device globals; no allocation allowed) ----------
// q,k,v,scan stored as [s][b][e] with e = h*64+d  (contiguous per (s,b) row)
// gate, y stored as [b][s][e] (row m = b*S+s)
__device__ float g_q[S_ * B_ * E_];
__device__ float g_k[S_ * B_ * E_];
__device__ float g_v[S_ * B_ * E_];
__device__ float g_gate[B_ * S_ * E_];
__device__ float g_scan[S_ * B_ * E_];
__device__ float g_y[B_ * S_ * E_];

// ---------------------------------------------------------------------------
// Generic fp32 GEMM: C[m,n] = sum_k A[m,k] * Bmat[n,k]   (both K-major)
// mode 1: A = x, N=4096 stacked (Wq|Wk|Wv|Wg), routed epilogue into
//         g_q/g_k/g_v ([s][b][e]) and g_gate ([b][s][e]).
// mode 0: A = g_y, Bmat = Wo, plain store to C (d_out).
// Tiles: 128x128x8, 256 threads, 8x8 per thread.
// ---------------------------------------------------------------------------
__global__ void __launch_bounds__(256)
gemm_kernel(const float* __restrict__ A,
            const float* __restrict__ W0, const float* __restrict__ W1,
            const float* __restrict__ W2, const float* __restrict__ W3,
            float* __restrict__ C, int K, int mode)
{
    __shared__ float As[8][128];
    __shared__ float Bs[8][128];

    const int tid = threadIdx.x;
    const int bm = blockIdx.y, bn = blockIdx.x;
    const int nbase = bn * 128;

    const float* Ap = (A != nullptr) ? A : g_y;

    const float* Bmat;
    int frow;
    if (mode == 1) {
        int p = nbase >> 10;
        Bmat = (p == 0) ? W0 : (p == 1) ? W1 : (p == 2) ? W2 : W3;
        frow = nbase & 1023;
    } else {
        Bmat = W0;
        frow = nbase;
    }

    const int lm = tid >> 1;          // 0..127
    const int lk = (tid & 1) * 4;     // 0 or 4

    float acc[8][8];
#pragma unroll
    for (int i = 0; i < 8; i++)
#pragma unroll
        for (int j = 0; j < 8; j++) acc[i][j] = 0.f;

    const int tm = (tid >> 4) * 8;
    const int tn = (tid & 15) * 8;

    for (int k0 = 0; k0 < K; k0 += 8) {
        float4 a4 = *(const float4*)(Ap + (size_t)(bm * 128 + lm) * K + k0 + lk);
        float4 b4 = *(const float4*)(Bmat + (size_t)(frow + lm) * K + k0 + lk);
        As[lk + 0][lm] = a4.x; As[lk + 1][lm] = a4.y;
        As[lk + 2][lm] = a4.z; As[lk + 3][lm] = a4.w;
        Bs[lk + 0][lm] = b4.x; Bs[lk + 1][lm] = b4.y;
        Bs[lk + 2][lm] = b4.z; Bs[lk + 3][lm] = b4.w;
        __syncthreads();
#pragma unroll
        for (int kk = 0; kk < 8; kk++) {
            float a[8], b[8];
#pragma unroll
            for (int i = 0; i < 8; i++) a[i] = As[kk][tm + i];
#pragma unroll
            for (int j = 0; j < 8; j++) b[j] = Bs[kk][tn + j];
#pragma unroll
            for (int i = 0; i < 8; i++)
#pragma unroll
                for (int j = 0; j < 8; j++) acc[i][j] += a[i] * b[j];
        }
        __syncthreads();
    }

    if (mode == 0) {
#pragma unroll
        for (int i = 0; i < 8; i++) {
            int m = bm * 128 + tm + i;
            float* crow = C + (size_t)m * 1024 + nbase + tn;
#pragma unroll
            for (int j = 0; j < 8; j++) crow[j] = acc[i][j];
        }
    } else {
        int p = nbase >> 10;
        int f = (nbase & 1023) + tn;
#pragma unroll
        for (int i = 0; i < 8; i++) {
            int m = bm * 128 + tm + i;
            int b = m >> 11;       // m / 2048  (S=2048)
            int s = m & 2047;
            if (p == 3) {
                float* dst = g_gate + (size_t)m * 1024 + f;
#pragma unroll
                for (int j = 0; j < 8; j++) dst[j] = acc[i][j];
            } else {
                float* dst = (p == 0 ? g_q : p == 1 ? g_k : g_v)
                             + (size_t)(s * B_ + b) * 1024 + f;
#pragma unroll
                for (int j = 0; j < 8; j++) dst[j] = acc[i][j];
            }
        }
    }
}

// ---------------------------------------------------------------------------
// TTT scan: one block per head (16 blocks), 256 threads = (b,e) with b=tid/64.
// Params (W 64x64, bias, g, bl) live in smem; 2 SGD steps + final apply/token.
// ---------------------------------------------------------------------------
__global__ void __launch_bounds__(256)
scan_kernel(const float* __restrict__ fw_W, const float* __restrict__ fw_b,
            const float* __restrict__ fw_g, const float* __restrict__ fw_bl,
            const float* __restrict__ ttt_g, const float* __restrict__ ttt_b)
{
    __shared__ float Ws[D_ * D_];
    __shared__ float bias[D_], gs[D_], bls[D_], ttg[D_], ttb[D_];
    __shared__ float ks[B_][D_], ts[B_][D_];
    __shared__ float dps[B_][D_], dpx[B_][D_], dhs[B_][D_];
    __shared__ float redA[8][2], redB[8][2];

    const int h = blockIdx.x;
    const int tid = threadIdx.x;
    const int b = tid >> 6;
    const int e = tid & 63;
    const int warp = tid >> 5;
    const int lane = tid & 31;

    for (int i = tid; i < D_ * D_; i += 256) Ws[i] = fw_W[h * D_ * D_ + i];
    if (tid < 64) {
        bias[tid] = fw_b[h * 64 + tid];
        gs[tid]   = fw_g[h * 64 + tid];
        bls[tid]  = fw_bl[h * 64 + tid];
        ttg[tid]  = ttt_g[h * 64 + tid];
        ttb[tid]  = ttt_b[h * 64 + tid];
    }
    __syncthreads();

    const float c = 2.0f / (float)(B_ * H_ * D_);   // d(mean MSE)/d(pred)

    for (int s = 0; s < S_; s++) {
        const size_t base = (size_t)(s * B_ + b) * E_ + h * 64 + e;
        float kv = g_k[base];
        ks[b][e] = kv;
        ts[b][e] = g_v[base] - kv;    // target = v - k
        __syncthreads();

        float xh = 0.f;

        for (int step = 0; step < 3; step++) {
            // ---- forward: h = k @ W + bias, then LN ----
            float acc = bias[e];
#pragma unroll
            for (int d = 0; d < 64; d++) acc += ks[b][d] * Ws[d * 64 + e];

            float sum = acc, sq = acc * acc;
#pragma unroll
            for (int o = 16; o > 0; o >>= 1) {
                sum += __shfl_xor_sync(~0u, sum, o);
                sq  += __shfl_xor_sync(~0u, sq, o);
            }
            if (lane == 0) { redA[warp][0] = sum; redA[warp][1] = sq; }
            __syncthreads();
            float fsum = redA[b * 2][0] + redA[b * 2 + 1][0];
            float fsq  = redA[b * 2][1] + redA[b * 2 + 1][1];
            float mu   = fsum * (1.0f / 64.0f);
            float var  = fsq * (1.0f / 64.0f) - mu * mu;
            float rstd = rsqrtf(var + LN_EPS);
            xh = (acc - mu) * rstd;

            if (step == 2) break;   // final apply: no gradient

            // ---- backward ----
            float pred  = xh * gs[e] + bls[e];
            float dpred = c * (pred - ts[b][e]);
            float dxh   = dpred * gs[e];

            float s1 = dxh, s2 = dxh * xh;
#pragma unroll
            for (int o = 16; o > 0; o >>= 1) {
                s1 += __shfl_xor_sync(~0u, s1, o);
                s2 += __shfl_xor_sync(~0u, s2, o);
            }
            if (lane == 0) { redB[warp][0] = s1; redB[warp][1] = s2; }
            __syncthreads();
            float S1 = redB[b * 2][0] + redB[b * 2 + 1][0];
            float S2 = redB[b * 2][1] + redB[b * 2 + 1][1];
            float dh = rstd * (dxh - (S1 + xh * S2) * (1.0f / 64.0f));

            dps[b][e] = dpred;
            dpx[b][e] = dpred * xh;
            dhs[b][e] = dh;
            __syncthreads();

            // ---- SGD updates ----
            if (tid < 64) {
                float dbl = 0.f, dg = 0.f, db = 0.f;
#pragma unroll
                for (int bb = 0; bb < 4; bb++) {
                    dbl += dps[bb][tid];
                    dg  += dpx[bb][tid];
                    db  += dhs[bb][tid];
                }
                bls[tid]  -= LR * dbl;
                gs[tid]   -= LR * dg;
                bias[tid] -= LR * db;
            }
#pragma unroll
            for (int i = 0; i < 16; i++) {
                int idx = i * 256 + tid;
                int dd = idx >> 6, ee = idx & 63;
                float dw = ks[0][dd] * dhs[0][ee] + ks[1][dd] * dhs[1][ee]
                         + ks[2][dd] * dhs[2][ee] + ks[3][dd] * dhs[3][ee];
                Ws[idx] -= LR * dw;
            }
            __syncthreads();
        }

        // ---- final: pred = xh*g + bl, second LN, ttt scale, add q ----
        float pred = xh * gs[e] + bls[e];
        float sum = pred, sq = pred * pred;
#pragma unroll
        for (int o = 16; o > 0; o >>= 1) {
            sum += __shfl_xor_sync(~0u, sum, o);
            sq  += __shfl_xor_sync(~0u, sq, o);
        }
        if (lane == 0) { redB[warp][0] = sum; redB[warp][1] = sq; }
        __syncthreads();
        float fsum = redB[b * 2][0] + redB[b * 2 + 1][0];
        float fsq  = redB[b * 2][1] + redB[b * 2 + 1][1];
        float mu = fsum * (1.0f / 64.0f);
        float rs = rsqrtf(fsq * (1.0f / 64.0f) - mu * mu + LN_EPS);
        float z = (pred - mu) * rs * ttg[e] + ttb[e];

        g_scan[base] = g_q[base] + z;
        __syncthreads();   // protect ks/ts/red before next token
    }
}

// ---------------------------------------------------------------------------
// Post: per (b,s) row — LN over E, *post_g+post_b, * gelu(gate_pre) -> g_y
// ---------------------------------------------------------------------------
__global__ void __launch_bounds__(256)
post_kernel(const float* __restrict__ post_g, const float* __restrict__ post_b)
{
    __shared__ float red[8][2];
    const int row = blockIdx.x;          // b*S + s
    const int b = row >> 11;
    const int s = row & 2047;
    const float* in = g_scan + (size_t)(s * B_ + b) * E_;
    const float* gp = g_gate + (size_t)row * E_;
    float* out = g_y + (size_t)row * E_;

    const int tid = threadIdx.x, warp = tid >> 5, lane = tid & 31;
    float vals[4];
    float sum = 0.f, sq = 0.f;
#pragma unroll
    for (int i = 0; i < 4; i++) {
        float x = in[tid + 256 * i];
        vals[i] = x; sum += x; sq += x * x;
    }
#pragma unroll
    for (int o = 16; o > 0; o >>= 1) {
        sum += __shfl_xor_sync(~0u, sum, o);
        sq  += __shfl_xor_sync(~0u, sq, o);
    }
    if (lane == 0) { red[warp][0] = sum; red[warp][1] = sq; }
    __syncthreads();
    float fs = 0.f, fq = 0.f;
#pragma unroll
    for (int w = 0; w < 8; w++) { fs += red[w][0]; fq += red[w][1]; }
    float mu = fs * (1.0f / 1024.0f);
    float rs = rsqrtf(fq * (1.0f / 1024.0f) - mu * mu + LN_EPS);

#pragma unroll
    for (int i = 0; i < 4; i++) {
        int e = tid + 256 * i;
        float xh = (vals[i] - mu) * rs * post_g[e] + post_b[e];
        float x = gp[e];
        float t = 0.7978845608028654f * (x + 0.044715f * x * x * x);
        float gelu = 0.5f * x * (1.0f + tanhf(t));
        out[e] = gelu * xh;
    }
}

// ---------------------------------------------------------------------------
extern "C" void kernel_launch(void* const* d_in, const int* in_sizes, int n_in,
                              void* d_out, int out_size)
{
    const float* x      = (const float*)d_in[0];
    const float* Wq     = (const float*)d_in[1];
    const float* Wk     = (const float*)d_in[2];
    const float* Wv     = (const float*)d_in[3];
    const float* Wo     = (const float*)d_in[4];
    const float* Wg     = (const float*)d_in[5];
    const float* fw_W   = (const float*)d_in[6];
    const float* fw_b   = (const float*)d_in[7];
    const float* fw_g   = (const float*)d_in[8];
    const float* fw_bl  = (const float*)d_in[9];
    const float* ttt_g  = (const float*)d_in[10];
    const float* ttt_b  = (const float*)d_in[11];
    const float* post_g = (const float*)d_in[12];
    const float* post_b = (const float*)d_in[13];

    // 1) fused q/k/v/gate projections: [8192,1024] x [4096,1024]^T
    gemm_kernel<<<dim3(32, 64), 256>>>(x, Wq, Wk, Wv, Wg, nullptr, E_, 1);

    // 2) sequential TTT scan: one block per head
    scan_kernel<<<H_, 256>>>(fw_W, fw_b, fw_g, fw_bl, ttt_g, ttt_b);

    // 3) post-norm + gelu gating
    post_kernel<<<B_ * S_, 256>>>(post_g, post_b);

    // 4) output projection: [8192,1024] x [1024,1024]^T -> d_out
    gemm_kernel<<<dim3(8, 64), 256>>>(nullptr, Wo, Wo, Wo, Wo,
                                      (float*)d_out, E_, 0);
}

// round 3
// speedup vs baseline: 1.7912x; 1.7912x over previous
#include <cuda_runtime.h>
#include <cstdint>

#define B_ 4
#define S_ 2048
#define E_ 1024
#define H_ 16
#define D_ 64
#define LN_EPS 1e-5f
#define LR 0.1f

// ---------------- scratch (device globals; no allocation allowed) ----------
// q,k,v,scan stored as [s][b][e] with e = h*64+d  (contiguous per (s,b) row)
// gate, y stored as [b][s][e] (row m = b*S+s)
__device__ float g_q[S_ * B_ * E_];
__device__ float g_k[S_ * B_ * E_];
__device__ float g_v[S_ * B_ * E_];
__device__ float g_gate[B_ * S_ * E_];
__device__ float g_scan[S_ * B_ * E_];
__device__ float g_y[B_ * S_ * E_];

// ---------------------------------------------------------------------------
// Generic fp32 GEMM: C[m,n] = sum_k A[m,k] * Bmat[n,k]   (both K-major)
// mode 1: A = x, N=4096 stacked (Wq|Wk|Wv|Wg) -> g_q/g_k/g_v/g_gate
// mode 0: A = g_y, Bmat = Wo -> C (d_out)
// ---------------------------------------------------------------------------
__global__ void __launch_bounds__(256)
gemm_kernel(const float* __restrict__ A,
            const float* __restrict__ W0, const float* __restrict__ W1,
            const float* __restrict__ W2, const float* __restrict__ W3,
            float* __restrict__ C, int K, int mode)
{
    __shared__ float As[8][128];
    __shared__ float Bs[8][128];

    const int tid = threadIdx.x;
    const int bm = blockIdx.y, bn = blockIdx.x;
    const int nbase = bn * 128;

    const float* Ap = (A != nullptr) ? A : g_y;

    const float* Bmat;
    int frow;
    if (mode == 1) {
        int p = nbase >> 10;
        Bmat = (p == 0) ? W0 : (p == 1) ? W1 : (p == 2) ? W2 : W3;
        frow = nbase & 1023;
    } else {
        Bmat = W0;
        frow = nbase;
    }

    const int lm = tid >> 1;
    const int lk = (tid & 1) * 4;

    float acc[8][8];
#pragma unroll
    for (int i = 0; i < 8; i++)
#pragma unroll
        for (int j = 0; j < 8; j++) acc[i][j] = 0.f;

    const int tm = (tid >> 4) * 8;
    const int tn = (tid & 15) * 8;

    for (int k0 = 0; k0 < K; k0 += 8) {
        float4 a4 = *(const float4*)(Ap + (size_t)(bm * 128 + lm) * K + k0 + lk);
        float4 b4 = *(const float4*)(Bmat + (size_t)(frow + lm) * K + k0 + lk);
        As[lk + 0][lm] = a4.x; As[lk + 1][lm] = a4.y;
        As[lk + 2][lm] = a4.z; As[lk + 3][lm] = a4.w;
        Bs[lk + 0][lm] = b4.x; Bs[lk + 1][lm] = b4.y;
        Bs[lk + 2][lm] = b4.z; Bs[lk + 3][lm] = b4.w;
        __syncthreads();
#pragma unroll
        for (int kk = 0; kk < 8; kk++) {
            float a[8], b[8];
#pragma unroll
            for (int i = 0; i < 8; i++) a[i] = As[kk][tm + i];
#pragma unroll
            for (int j = 0; j < 8; j++) b[j] = Bs[kk][tn + j];
#pragma unroll
            for (int i = 0; i < 8; i++)
#pragma unroll
                for (int j = 0; j < 8; j++) acc[i][j] += a[i] * b[j];
        }
        __syncthreads();
    }

    if (mode == 0) {
#pragma unroll
        for (int i = 0; i < 8; i++) {
            int m = bm * 128 + tm + i;
            float* crow = C + (size_t)m * 1024 + nbase + tn;
#pragma unroll
            for (int j = 0; j < 8; j++) crow[j] = acc[i][j];
        }
    } else {
        int p = nbase >> 10;
        int f = (nbase & 1023) + tn;
#pragma unroll
        for (int i = 0; i < 8; i++) {
            int m = bm * 128 + tm + i;
            int b = m >> 11;
            int s = m & 2047;
            if (p == 3) {
                float* dst = g_gate + (size_t)m * 1024 + f;
#pragma unroll
                for (int j = 0; j < 8; j++) dst[j] = acc[i][j];
            } else {
                float* dst = (p == 0 ? g_q : p == 1 ? g_k : g_v)
                             + (size_t)(s * B_ + b) * 1024 + f;
#pragma unroll
                for (int j = 0; j < 8; j++) dst[j] = acc[i][j];
            }
        }
    }
}

// ---------------------------------------------------------------------------
// TTT scan, v2: W register-resident (16 floats/thread), warp-local LN
// (warp b owns batch b, 2 elems/lane), k/v prefetched one token ahead.
// One block per head; 6 barriers/token.
// ---------------------------------------------------------------------------
__global__ void __launch_bounds__(256)
scan_kernel(const float* __restrict__ fw_W, const float* __restrict__ fw_b,
            const float* __restrict__ fw_g, const float* __restrict__ fw_bl,
            const float* __restrict__ ttt_g, const float* __restrict__ ttt_b)
{
    __shared__ __align__(16) float ks[B_][D_];
    __shared__ __align__(16) float ts[B_][D_];
    __shared__ __align__(16) float pt[4][B_][D_];   // partials [dgrp][b][e]
    __shared__ float dhs[B_][D_], dps[B_][D_], dpx[B_][D_];
    __shared__ float bias[D_], gs[D_], bls[D_], ttg[D_], ttb[D_];

    const int h    = blockIdx.x;
    const int tid  = threadIdx.x;
    const int warp = tid >> 5;
    const int lane = tid & 31;
    const int dgrp = tid >> 6;        // W-owner: rows dgrp*16..+15
    const int eW   = tid & 63;        // W-owner: column e
    const int lb   = tid >> 6;        // loader batch
    const int le   = tid & 63;        // loader element

    // W resident in registers: Wreg[j] = W[dgrp*16+j][eW]
    float Wreg[16];
#pragma unroll
    for (int j = 0; j < 16; j++)
        Wreg[j] = fw_W[h * 4096 + (dgrp * 16 + j) * 64 + eW];
    if (tid < 64) {
        bias[tid] = fw_b[h * 64 + tid];
        gs[tid]   = fw_g[h * 64 + tid];
        bls[tid]  = fw_bl[h * 64 + tid];
        ttg[tid]  = ttt_g[h * 64 + tid];
        ttb[tid]  = ttt_b[h * 64 + tid];
    }

    // prefetch token 0
    size_t pb = (size_t)lb * E_ + h * 64 + le;
    float kf = g_k[pb];
    float vf = g_v[pb];

    const float c = 2.0f / (float)(B_ * H_ * D_);

    for (int s = 0; s < S_; s++) {
        ks[lb][le] = kf;
        ts[lb][le] = vf - kf;
        __syncthreads();                                    // [1]

        if (s + 1 < S_) {
            size_t nb = (size_t)((s + 1) * B_ + lb) * E_ + h * 64 + le;
            kf = g_k[nb];
            vf = g_v[nb];
        }
        float q0 = 0.f, q1 = 0.f;
        if (warp < 4) {
            size_t qb = (size_t)(s * B_ + warp) * E_ + h * 64 + lane;
            q0 = g_q[qb];
            q1 = g_q[qb + 32];
        }

        float xh0 = 0.f, xh1 = 0.f, rstd = 0.f;

        for (int step = 0; step < 3; step++) {
            // ---- forward partials: all 256 threads ----
            float a0 = 0.f, a1 = 0.f, a2 = 0.f, a3 = 0.f;
#pragma unroll
            for (int j4 = 0; j4 < 4; j4++) {
                float4 k0v = *(const float4*)&ks[0][dgrp * 16 + j4 * 4];
                float4 k1v = *(const float4*)&ks[1][dgrp * 16 + j4 * 4];
                float4 k2v = *(const float4*)&ks[2][dgrp * 16 + j4 * 4];
                float4 k3v = *(const float4*)&ks[3][dgrp * 16 + j4 * 4];
                float w0 = Wreg[j4 * 4 + 0], w1 = Wreg[j4 * 4 + 1];
                float w2 = Wreg[j4 * 4 + 2], w3 = Wreg[j4 * 4 + 3];
                a0 += k0v.x * w0 + k0v.y * w1 + k0v.z * w2 + k0v.w * w3;
                a1 += k1v.x * w0 + k1v.y * w1 + k1v.z * w2 + k1v.w * w3;
                a2 += k2v.x * w0 + k2v.y * w1 + k2v.z * w2 + k2v.w * w3;
                a3 += k3v.x * w0 + k3v.y * w1 + k3v.z * w2 + k3v.w * w3;
            }
            pt[dgrp][0][eW] = a0;
            pt[dgrp][1][eW] = a1;
            pt[dgrp][2][eW] = a2;
            pt[dgrp][3][eW] = a3;
            __syncthreads();                                // [2]/[4] etc.

            // ---- combine + LN: warp b handles batch b (2 elems/lane) ----
            if (warp < 4) {
                const int b = warp;
                float h0 = bias[lane] + pt[0][b][lane] + pt[1][b][lane]
                         + pt[2][b][lane] + pt[3][b][lane];
                float h1 = bias[lane + 32] + pt[0][b][lane + 32] + pt[1][b][lane + 32]
                         + pt[2][b][lane + 32] + pt[3][b][lane + 32];
                float sum = h0 + h1, sq = h0 * h0 + h1 * h1;
#pragma unroll
                for (int o = 16; o > 0; o >>= 1) {
                    sum += __shfl_xor_sync(~0u, sum, o);
                    sq  += __shfl_xor_sync(~0u, sq, o);
                }
                float mu  = sum * (1.0f / 64.0f);
                float var = sq * (1.0f / 64.0f) - mu * mu;
                rstd = rsqrtf(var + LN_EPS);
                xh0 = (h0 - mu) * rstd;
                xh1 = (h1 - mu) * rstd;
            }
            if (step == 2) break;

            // ---- backward (warp-local LN grad) ----
            if (warp < 4) {
                const int b = warp;
                float g0 = gs[lane], g1 = gs[lane + 32];
                float p0 = xh0 * g0 + bls[lane];
                float p1 = xh1 * g1 + bls[lane + 32];
                float dp0 = c * (p0 - ts[b][lane]);
                float dp1 = c * (p1 - ts[b][lane + 32]);
                float dx0 = dp0 * g0, dx1 = dp1 * g1;
                float S1 = dx0 + dx1;
                float S2 = dx0 * xh0 + dx1 * xh1;
#pragma unroll
                for (int o = 16; o > 0; o >>= 1) {
                    S1 += __shfl_xor_sync(~0u, S1, o);
                    S2 += __shfl_xor_sync(~0u, S2, o);
                }
                float dh0 = rstd * (dx0 - (S1 + xh0 * S2) * (1.0f / 64.0f));
                float dh1 = rstd * (dx1 - (S1 + xh1 * S2) * (1.0f / 64.0f));
                dhs[b][lane]      = dh0;
                dhs[b][lane + 32] = dh1;
                dps[b][lane]      = dp0;
                dps[b][lane + 32] = dp1;
                dpx[b][lane]      = dp0 * xh0;
                dpx[b][lane + 32] = dp1 * xh1;
            }
            __syncthreads();                                // [3]/[5]

            // ---- SGD: params (tid<64) + W (all threads, registers) ----
            if (tid < 64) {
                bias[tid] -= LR * (dhs[0][tid] + dhs[1][tid] + dhs[2][tid] + dhs[3][tid]);
                gs[tid]   -= LR * (dpx[0][tid] + dpx[1][tid] + dpx[2][tid] + dpx[3][tid]);
                bls[tid]  -= LR * (dps[0][tid] + dps[1][tid] + dps[2][tid] + dps[3][tid]);
            }
            float d0 = dhs[0][eW], d1 = dhs[1][eW], d2 = dhs[2][eW], d3 = dhs[3][eW];
#pragma unroll
            for (int j4 = 0; j4 < 4; j4++) {
                float4 k0v = *(const float4*)&ks[0][dgrp * 16 + j4 * 4];
                float4 k1v = *(const float4*)&ks[1][dgrp * 16 + j4 * 4];
                float4 k2v = *(const float4*)&ks[2][dgrp * 16 + j4 * 4];
                float4 k3v = *(const float4*)&ks[3][dgrp * 16 + j4 * 4];
                Wreg[j4 * 4 + 0] -= LR * (k0v.x * d0 + k1v.x * d1 + k2v.x * d2 + k3v.x * d3);
                Wreg[j4 * 4 + 1] -= LR * (k0v.y * d0 + k1v.y * d1 + k2v.y * d2 + k3v.y * d3);
                Wreg[j4 * 4 + 2] -= LR * (k0v.z * d0 + k1v.z * d1 + k2v.z * d2 + k3v.z * d3);
                Wreg[j4 * 4 + 3] -= LR * (k0v.w * d0 + k1v.w * d1 + k2v.w * d2 + k3v.w * d3);
            }
            // no barrier: next pt write is ordered behind this step's syncs
        }

        // ---- final: pred -> LN -> ttt scale -> +q -> store ----
        if (warp < 4) {
            const int b = warp;
            float p0 = xh0 * gs[lane] + bls[lane];
            float p1 = xh1 * gs[lane + 32] + bls[lane + 32];
            float sum = p0 + p1, sq = p0 * p0 + p1 * p1;
#pragma unroll
            for (int o = 16; o > 0; o >>= 1) {
                sum += __shfl_xor_sync(~0u, sum, o);
                sq  += __shfl_xor_sync(~0u, sq, o);
            }
            float mu = sum * (1.0f / 64.0f);
            float rs = rsqrtf(sq * (1.0f / 64.0f) - mu * mu + LN_EPS);
            size_t ob = (size_t)(s * B_ + b) * E_ + h * 64 + lane;
            g_scan[ob]      = q0 + (p0 - mu) * rs * ttg[lane] + ttb[lane];
            g_scan[ob + 32] = q1 + (p1 - mu) * rs * ttg[lane + 32] + ttb[lane + 32];
        }
        // ks/ts rewrite at loop top races nothing: all ks/ts readers finished
        // before the final partials barrier; barrier [1] orders the new writes.
    }
}

// ---------------------------------------------------------------------------
// Post: per (b,s) row — LN over E, *post_g+post_b, * gelu(gate_pre) -> g_y
// ---------------------------------------------------------------------------
__global__ void __launch_bounds__(256)
post_kernel(const float* __restrict__ post_g, const float* __restrict__ post_b)
{
    __shared__ float red[8][2];
    const int row = blockIdx.x;
    const int b = row >> 11;
    const int s = row & 2047;
    const float* in = g_scan + (size_t)(s * B_ + b) * E_;
    const float* gp = g_gate + (size_t)row * E_;
    float* out = g_y + (size_t)row * E_;

    const int tid = threadIdx.x, warp = tid >> 5, lane = tid & 31;
    float vals[4];
    float sum = 0.f, sq = 0.f;
#pragma unroll
    for (int i = 0; i < 4; i++) {
        float x = in[tid + 256 * i];
        vals[i] = x; sum += x; sq += x * x;
    }
#pragma unroll
    for (int o = 16; o > 0; o >>= 1) {
        sum += __shfl_xor_sync(~0u, sum, o);
        sq  += __shfl_xor_sync(~0u, sq, o);
    }
    if (lane == 0) { red[warp][0] = sum; red[warp][1] = sq; }
    __syncthreads();
    float fs = 0.f, fq = 0.f;
#pragma unroll
    for (int w = 0; w < 8; w++) { fs += red[w][0]; fq += red[w][1]; }
    float mu = fs * (1.0f / 1024.0f);
    float rs = rsqrtf(fq * (1.0f / 1024.0f) - mu * mu + LN_EPS);

#pragma unroll
    for (int i = 0; i < 4; i++) {
        int e = tid + 256 * i;
        float xh = (vals[i] - mu) * rs * post_g[e] + post_b[e];
        float x = gp[e];
        float t = 0.7978845608028654f * (x + 0.044715f * x * x * x);
        float gelu = 0.5f * x * (1.0f + tanhf(t));
        out[e] = gelu * xh;
    }
}

// ---------------------------------------------------------------------------
extern "C" void kernel_launch(void* const* d_in, const int* in_sizes, int n_in,
                              void* d_out, int out_size)
{
    const float* x      = (const float*)d_in[0];
    const float* Wq     = (const float*)d_in[1];
    const float* Wk     = (const float*)d_in[2];
    const float* Wv     = (const float*)d_in[3];
    const float* Wo     = (const float*)d_in[4];
    const float* Wg     = (const float*)d_in[5];
    const float* fw_W   = (const float*)d_in[6];
    const float* fw_b   = (const float*)d_in[7];
    const float* fw_g   = (const float*)d_in[8];
    const float* fw_bl  = (const float*)d_in[9];
    const float* ttt_g  = (const float*)d_in[10];
    const float* ttt_b  = (const float*)d_in[11];
    const float* post_g = (const float*)d_in[12];
    const float* post_b = (const float*)d_in[13];

    gemm_kernel<<<dim3(32, 64), 256>>>(x, Wq, Wk, Wv, Wg, nullptr, E_, 1);
    scan_kernel<<<H_, 256>>>(fw_W, fw_b, fw_g, fw_bl, ttt_g, ttt_b);
    post_kernel<<<B_ * S_, 256>>>(post_g, post_b);
    gemm_kernel<<<dim3(8, 64), 256>>>(nullptr, Wo, Wo, Wo, Wo,
                                      (float*)d_out, E_, 0);
}

// round 5
// speedup vs baseline: 2.2001x; 1.2283x over previous
#include <cuda_runtime.h>
#include <cstdint>

#define B_ 4
#define S_ 2048
#define E_ 1024
#define H_ 16
#define D_ 64
#define LN_EPS 1e-5f
#define LR 0.1f
#define INV64 0.015625f
#define C_GRAD (2.0f / 4096.0f)   // 2/(B*H*D)

// ---------------- scratch (device globals; no allocation allowed) ----------
// q,k,v,scan stored as [s][b][e] with e = h*64+d
// gate, y stored as [b][s][e]
__device__ float g_q[S_ * B_ * E_];
__device__ float g_k[S_ * B_ * E_];
__device__ float g_v[S_ * B_ * E_];
__device__ float g_gate[B_ * S_ * E_];
__device__ float g_scan[S_ * B_ * E_];
__device__ float g_y[B_ * S_ * E_];

// ---------------------------------------------------------------------------
// fp32 GEMM, 128x128x8 tiles, 2-stage smem double buffer (1 barrier/tile).
// mode 1: A = x, N=4096 stacked (Wq|Wk|Wv|Wg) -> g_q/g_k/g_v/g_gate
// mode 0: A = g_y, Bmat = Wo -> C (d_out)
// ---------------------------------------------------------------------------
__global__ void __launch_bounds__(256)
gemm_kernel(const float* __restrict__ A,
            const float* __restrict__ W0, const float* __restrict__ W1,
            const float* __restrict__ W2, const float* __restrict__ W3,
            float* __restrict__ C, int K, int mode)
{
    __shared__ float As[2][8][128];
    __shared__ float Bs[2][8][128];

    const int tid = threadIdx.x;
    const int bm = blockIdx.y, bn = blockIdx.x;
    const int nbase = bn * 128;

    const float* Ap = (A != nullptr) ? A : g_y;

    const float* Bmat;
    int frow;
    if (mode == 1) {
        int p = nbase >> 10;
        Bmat = (p == 0) ? W0 : (p == 1) ? W1 : (p == 2) ? W2 : W3;
        frow = nbase & 1023;
    } else {
        Bmat = W0;
        frow = nbase;
    }

    const int lm = tid >> 1;          // 0..127
    const int lk = (tid & 1) * 4;     // 0 or 4

    const float* Arow = Ap + (size_t)(bm * 128 + lm) * K + lk;
    const float* Brow = Bmat + (size_t)(frow + lm) * K + lk;

    float acc[8][8];
#pragma unroll
    for (int i = 0; i < 8; i++)
#pragma unroll
        for (int j = 0; j < 8; j++) acc[i][j] = 0.f;

    const int tm = (tid >> 4) * 8;
    const int tn = (tid & 15) * 8;

    const int NT = K >> 3;

    // preload tile 0
    {
        float4 a4 = *(const float4*)(Arow);
        float4 b4 = *(const float4*)(Brow);
        As[0][lk + 0][lm] = a4.x; As[0][lk + 1][lm] = a4.y;
        As[0][lk + 2][lm] = a4.z; As[0][lk + 3][lm] = a4.w;
        Bs[0][lk + 0][lm] = b4.x; Bs[0][lk + 1][lm] = b4.y;
        Bs[0][lk + 2][lm] = b4.z; Bs[0][lk + 3][lm] = b4.w;
    }
    __syncthreads();

    for (int t = 0; t < NT; t++) {
        const int cur = t & 1, nxt = cur ^ 1;

        float4 a4, b4;
        const bool more = (t + 1 < NT);
        if (more) {
            a4 = *(const float4*)(Arow + (t + 1) * 8);
            b4 = *(const float4*)(Brow + (t + 1) * 8);
        }

#pragma unroll
        for (int kk = 0; kk < 8; kk++) {
            float a[8], b[8];
#pragma unroll
            for (int i = 0; i < 8; i++) a[i] = As[cur][kk][tm + i];
#pragma unroll
            for (int j = 0; j < 8; j++) b[j] = Bs[cur][kk][tn + j];
#pragma unroll
            for (int i = 0; i < 8; i++)
#pragma unroll
                for (int j = 0; j < 8; j++) acc[i][j] += a[i] * b[j];
        }

        if (more) {
            As[nxt][lk + 0][lm] = a4.x; As[nxt][lk + 1][lm] = a4.y;
            As[nxt][lk + 2][lm] = a4.z; As[nxt][lk + 3][lm] = a4.w;
            Bs[nxt][lk + 0][lm] = b4.x; Bs[nxt][lk + 1][lm] = b4.y;
            Bs[nxt][lk + 2][lm] = b4.z; Bs[nxt][lk + 3][lm] = b4.w;
        }
        __syncthreads();
    }

    if (mode == 0) {
#pragma unroll
        for (int i = 0; i < 8; i++) {
            int m = bm * 128 + tm + i;
            float* crow = C + (size_t)m * 1024 + nbase + tn;
#pragma unroll
            for (int j = 0; j < 8; j++) crow[j] = acc[i][j];
        }
    } else {
        int p = nbase >> 10;
        int f = (nbase & 1023) + tn;
#pragma unroll
        for (int i = 0; i < 8; i++) {
            int m = bm * 128 + tm + i;
            int b = m >> 11;
            int s = m & 2047;
            if (p == 3) {
                float* dst = g_gate + (size_t)m * 1024 + f;
#pragma unroll
                for (int j = 0; j < 8; j++) dst[j] = acc[i][j];
            } else {
                float* dst = (p == 0 ? g_q : p == 1 ? g_k : g_v)
                             + (size_t)(s * B_ + b) * 1024 + f;
#pragma unroll
                for (int j = 0; j < 8; j++) dst[j] = acc[i][j];
            }
        }
    }
}

// ---------------------------------------------------------------------------
__device__ __forceinline__ void bfly2(float& a, float& b)
{
#pragma unroll
    for (int o = 16; o > 0; o >>= 1) {
        a += __shfl_xor_sync(0xffffffffu, a, o);
        b += __shfl_xor_sync(0xffffffffu, b, o);
    }
}
__device__ __forceinline__ void bfly4(float& a, float& b, float& c, float& d)
{
#pragma unroll
    for (int o = 16; o > 0; o >>= 1) {
        a += __shfl_xor_sync(0xffffffffu, a, o);
        b += __shfl_xor_sync(0xffffffffu, b, o);
        c += __shfl_xor_sync(0xffffffffu, c, o);
        d += __shfl_xor_sync(0xffffffffu, d, o);
    }
}

#define BAR_A()    asm volatile("bar.sync 1, 128;" ::: "memory")
#define BAR_FULL() asm volatile("bar.sync 0, 256;" ::: "memory")

// ---------------------------------------------------------------------------
// TTT scan v3: Gram-matrix reformulation + warp specialization.
// Group A (warps 0-3): W (32 regs/thread), matvec, LN1/bwd1/LN2/bwd2, W update.
// Group B (warps 4-7): Gram 4x4, final-apply (LN3 + LN4), +q, store.
// ---------------------------------------------------------------------------
__global__ void __launch_bounds__(256)
scan_kernel(const float* __restrict__ fw_W, const float* __restrict__ fw_b,
            const float* __restrict__ fw_g, const float* __restrict__ fw_bl,
            const float* __restrict__ ttt_g, const float* __restrict__ ttt_b)
{
    __shared__ __align__(16) float ks[2][B_][D_];
    __shared__ __align__(16) float ts[2][B_][D_];
    __shared__ __align__(16) float pt[2][B_][D_];
    __shared__ float d1h[B_][D_];
    __shared__ float d1x[2][B_][D_], d1p[2][B_][D_];
    __shared__ float d2h[B_][D_], d2x[B_][D_], d2p[B_][D_];
    __shared__ float z2s[B_][D_], dsum[B_][D_];
    __shared__ float Ms[B_][B_];

    const int h = blockIdx.x;
    const int tid = threadIdx.x;
    const int l = tid & 31;
    const int hb = h * 64;

    if (tid < 128) {
        // ================= GROUP A =================
        const int aw   = tid >> 5;        // LN role: batch
        const int ecol = tid & 63;        // W role: column
        const int rgrp = tid >> 6;        // W role: row group (0/1)
        const int lb   = tid >> 6;        // loader: batches lb, lb+2
        const int le   = tid & 63;

        float Wreg[32];
#pragma unroll
        for (int j = 0; j < 32; j++)
            Wreg[j] = fw_W[h * 4096 + (rgrp * 32 + j) * 64 + ecol];

        float bias0 = fw_b[hb + l],  bias1 = fw_b[hb + l + 32];
        float g0    = fw_g[hb + l],  g1    = fw_g[hb + l + 32];
        float bl0   = fw_bl[hb + l], bl1   = fw_bl[hb + l + 32];

        float kf0 = g_k[(size_t)lb * E_ + hb + le];
        float kf1 = g_k[(size_t)(lb + 2) * E_ + hb + le];
        float vf0 = g_v[(size_t)lb * E_ + hb + le];
        float vf1 = g_v[(size_t)(lb + 2) * E_ + hb + le];

        for (int s = 0; s < S_; s++) {
            const int par = s & 1;
            ks[par][lb][le]     = kf0;
            ks[par][lb + 2][le] = kf1;
            ts[par][lb][le]     = vf0 - kf0;
            ts[par][lb + 2][le] = vf1 - kf1;
            BAR_A();

            if (s + 1 < S_) {
                size_t nb = (size_t)((s + 1) * B_ + lb) * E_ + hb + le;
                kf0 = g_k[nb]; kf1 = g_k[nb + 2 * E_];
                vf0 = g_v[nb]; vf1 = g_v[nb + 2 * E_];
            }

            // ---- matvec partials ----
            const float4* k40 = (const float4*)&ks[par][0][rgrp * 32];
            const float4* k41 = (const float4*)&ks[par][1][rgrp * 32];
            const float4* k42 = (const float4*)&ks[par][2][rgrp * 32];
            const float4* k43 = (const float4*)&ks[par][3][rgrp * 32];
            float a0 = 0.f, a1 = 0.f, a2 = 0.f, a3 = 0.f;
#pragma unroll
            for (int i = 0; i < 8; i++) {
                float4 c0 = k40[i], c1 = k41[i], c2 = k42[i], c3 = k43[i];
                float w0 = Wreg[4*i], w1 = Wreg[4*i+1], w2 = Wreg[4*i+2], w3 = Wreg[4*i+3];
                a0 += c0.x*w0 + c0.y*w1 + c0.z*w2 + c0.w*w3;
                a1 += c1.x*w0 + c1.y*w1 + c1.z*w2 + c1.w*w3;
                a2 += c2.x*w0 + c2.y*w1 + c2.z*w2 + c2.w*w3;
                a3 += c3.x*w0 + c3.y*w1 + c3.z*w2 + c3.w*w3;
            }
            pt[rgrp][0][ecol] = a0;
            pt[rgrp][1][ecol] = a1;
            pt[rgrp][2][ecol] = a2;
            pt[rgrp][3][ecol] = a3;
            BAR_A();

            // ---- combine + LN1 ----
            float z0 = bias0 + pt[0][aw][l]      + pt[1][aw][l];
            float z1 = bias1 + pt[0][aw][l + 32] + pt[1][aw][l + 32];
            float sum = z0 + z1, sq = z0 * z0 + z1 * z1;
            bfly2(sum, sq);
            float mu   = sum * INV64;
            float rstd = rsqrtf(sq * INV64 - mu * mu + LN_EPS);
            float xh0 = (z0 - mu) * rstd, xh1 = (z1 - mu) * rstd;

            // ---- bwd1 ----
            float t0 = ts[par][aw][l], t1 = ts[par][aw][l + 32];
            float p0 = xh0 * g0 + bl0, p1 = xh1 * g1 + bl1;
            float dp0 = C_GRAD * (p0 - t0), dp1 = C_GRAD * (p1 - t1);
            float dx0 = dp0 * g0, dx1 = dp1 * g1;
            float S1 = dx0 + dx1, S2 = dx0 * xh0 + dx1 * xh1;
            bfly2(S1, S2);
            float dh0 = rstd * (dx0 - (S1 + xh0 * S2) * INV64);
            float dh1 = rstd * (dx1 - (S1 + xh1 * S2) * INV64);
            d1h[aw][l]          = dh0;
            d1h[aw][l + 32]     = dh1;
            d1x[par][aw][l]      = dp0 * xh0;
            d1x[par][aw][l + 32] = dp1 * xh1;
            d1p[par][aw][l]      = dp0;
            d1p[par][aw][l + 32] = dp1;
            BAR_FULL();                                   // A3

            // ---- param update 1 (g2, bl2) ----
            float sx0 = d1x[par][0][l] + d1x[par][1][l] + d1x[par][2][l] + d1x[par][3][l];
            float sx1 = d1x[par][0][l+32] + d1x[par][1][l+32] + d1x[par][2][l+32] + d1x[par][3][l+32];
            float sp0 = d1p[par][0][l] + d1p[par][1][l] + d1p[par][2][l] + d1p[par][3][l];
            float sp1 = d1p[par][0][l+32] + d1p[par][1][l+32] + d1p[par][2][l+32] + d1p[par][3][l+32];
            g0 -= LR * sx0; g1 -= LR * sx1;
            bl0 -= LR * sp0; bl1 -= LR * sp1;

            // ---- corr2: z2 = z1 + sum_b' M[aw][b'] * dh1_b' ----
            float m0 = Ms[aw][0], m1 = Ms[aw][1], m2 = Ms[aw][2], m3 = Ms[aw][3];
            z0 += m0 * d1h[0][l] + m1 * d1h[1][l] + m2 * d1h[2][l] + m3 * d1h[3][l];
            z1 += m0 * d1h[0][l+32] + m1 * d1h[1][l+32] + m2 * d1h[2][l+32] + m3 * d1h[3][l+32];

            // ---- LN2 ----
            sum = z0 + z1; sq = z0 * z0 + z1 * z1;
            bfly2(sum, sq);
            mu   = sum * INV64;
            rstd = rsqrtf(sq * INV64 - mu * mu + LN_EPS);
            xh0 = (z0 - mu) * rstd; xh1 = (z1 - mu) * rstd;

            // ---- bwd2 (g2, bl2) ----
            p0 = xh0 * g0 + bl0; p1 = xh1 * g1 + bl1;
            dp0 = C_GRAD * (p0 - t0); dp1 = C_GRAD * (p1 - t1);
            dx0 = dp0 * g0; dx1 = dp1 * g1;
            S1 = dx0 + dx1; S2 = dx0 * xh0 + dx1 * xh1;
            bfly2(S1, S2);
            float e0 = rstd * (dx0 - (S1 + xh0 * S2) * INV64);
            float e1 = rstd * (dx1 - (S1 + xh1 * S2) * INV64);

            // ---- share2 ----
            z2s[aw][l]       = z0;   z2s[aw][l + 32]  = z1;
            d2h[aw][l]       = e0;   d2h[aw][l + 32]  = e1;
            d2x[aw][l]       = dp0 * xh0; d2x[aw][l + 32] = dp1 * xh1;
            d2p[aw][l]       = dp0;  d2p[aw][l + 32]  = dp1;
            dsum[aw][l]      = dh0 + e0;
            dsum[aw][l + 32] = dh1 + e1;
            BAR_FULL();                                   // S3

            // ---- param update 2 (g3, bl3, bias_next) ----
            sx0 = d2x[0][l] + d2x[1][l] + d2x[2][l] + d2x[3][l];
            sx1 = d2x[0][l+32] + d2x[1][l+32] + d2x[2][l+32] + d2x[3][l+32];
            sp0 = d2p[0][l] + d2p[1][l] + d2p[2][l] + d2p[3][l];
            sp1 = d2p[0][l+32] + d2p[1][l+32] + d2p[2][l+32] + d2p[3][l+32];
            g0 -= LR * sx0; g1 -= LR * sx1;
            bl0 -= LR * sp0; bl1 -= LR * sp1;
            bias0 -= LR * (dsum[0][l] + dsum[1][l] + dsum[2][l] + dsum[3][l]);
            bias1 -= LR * (dsum[0][l+32] + dsum[1][l+32] + dsum[2][l+32] + dsum[3][l+32]);

            // ---- W update ----
            float ds0 = LR * dsum[0][ecol];
            float ds1 = LR * dsum[1][ecol];
            float ds2 = LR * dsum[2][ecol];
            float ds3 = LR * dsum[3][ecol];
#pragma unroll
            for (int i = 0; i < 8; i++) {
                float4 c0 = k40[i], c1 = k41[i], c2 = k42[i], c3 = k43[i];
                Wreg[4*i]   -= c0.x*ds0 + c1.x*ds1 + c2.x*ds2 + c3.x*ds3;
                Wreg[4*i+1] -= c0.y*ds0 + c1.y*ds1 + c2.y*ds2 + c3.y*ds3;
                Wreg[4*i+2] -= c0.z*ds0 + c1.z*ds1 + c2.z*ds2 + c3.z*ds3;
                Wreg[4*i+3] -= c0.w*ds0 + c1.w*ds1 + c2.w*ds2 + c3.w*ds3;
            }
        }
    } else {
        // ================= GROUP B =================
        const int bw = (tid >> 5) - 4;    // batch

        float g0  = fw_g[hb + l],  g1  = fw_g[hb + l + 32];
        float bl0 = fw_bl[hb + l], bl1 = fw_bl[hb + l + 32];
        float tg0 = ttt_g[hb + l], tg1 = ttt_g[hb + l + 32];
        float tb0 = ttt_b[hb + l], tb1 = ttt_b[hb + l + 32];

        float kk0[4], kk1[4];
#pragma unroll
        for (int b = 0; b < 4; b++) {
            kk0[b] = g_k[(size_t)b * E_ + hb + l];
            kk1[b] = g_k[(size_t)b * E_ + hb + l + 32];
        }
        float Mreg[4];
        {
            float P0 = kk0[bw]*kk0[0] + kk1[bw]*kk1[0];
            float P1 = kk0[bw]*kk0[1] + kk1[bw]*kk1[1];
            float P2 = kk0[bw]*kk0[2] + kk1[bw]*kk1[2];
            float P3 = kk0[bw]*kk0[3] + kk1[bw]*kk1[3];
            bfly4(P0, P1, P2, P3);
            Mreg[0] = -LR * (P0 + 1.0f);
            Mreg[1] = -LR * (P1 + 1.0f);
            Mreg[2] = -LR * (P2 + 1.0f);
            Mreg[3] = -LR * (P3 + 1.0f);
            if (l == 0) {
                Ms[bw][0] = Mreg[0]; Ms[bw][1] = Mreg[1];
                Ms[bw][2] = Mreg[2]; Ms[bw][3] = Mreg[3];
            }
        }
        float q0 = g_q[(size_t)bw * E_ + hb + l];
        float q1 = g_q[(size_t)bw * E_ + hb + l + 32];
#pragma unroll
        for (int b = 0; b < 4; b++) {
            kk0[b] = g_k[(size_t)(1 * B_ + b) * E_ + hb + l];
            kk1[b] = g_k[(size_t)(1 * B_ + b) * E_ + hb + l + 32];
        }

        for (int s = 0; s < S_; s++) {
            BAR_FULL();                                   // A3
            BAR_FULL();                                   // S3
            const int par = s & 1;

            // ---- combined param update (g3, bl3) ----
            float sx0 = 0.f, sx1 = 0.f, sp0 = 0.f, sp1 = 0.f;
#pragma unroll
            for (int b = 0; b < 4; b++) {
                sx0 += d1x[par][b][l]      + d2x[b][l];
                sx1 += d1x[par][b][l + 32] + d2x[b][l + 32];
                sp0 += d1p[par][b][l]      + d2p[b][l];
                sp1 += d1p[par][b][l + 32] + d2p[b][l + 32];
            }
            g0 -= LR * sx0; g1 -= LR * sx1;
            bl0 -= LR * sp0; bl1 -= LR * sp1;

            // ---- corr3: z3 = z2 + sum_b' M[bw][b'] * dh2_b' ----
            float z0 = z2s[bw][l]
                     + Mreg[0]*d2h[0][l] + Mreg[1]*d2h[1][l]
                     + Mreg[2]*d2h[2][l] + Mreg[3]*d2h[3][l];
            float z1 = z2s[bw][l + 32]
                     + Mreg[0]*d2h[0][l+32] + Mreg[1]*d2h[1][l+32]
                     + Mreg[2]*d2h[2][l+32] + Mreg[3]*d2h[3][l+32];

            // ---- LN3 ----
            float sum = z0 + z1, sq = z0 * z0 + z1 * z1;
            bfly2(sum, sq);
            float mu = sum * INV64;
            float rs = rsqrtf(sq * INV64 - mu * mu + LN_EPS);
            float p0 = (z0 - mu) * rs * g0 + bl0;
            float p1 = (z1 - mu) * rs * g1 + bl1;

            // ---- LN4 (ttt_norm) + add q + store ----
            sum = p0 + p1; sq = p0 * p0 + p1 * p1;
            bfly2(sum, sq);
            mu = sum * INV64;
            rs = rsqrtf(sq * INV64 - mu * mu + LN_EPS);
            size_t ob = (size_t)(s * B_ + bw) * E_ + hb + l;
            g_scan[ob]      = q0 + (p0 - mu) * rs * tg0 + tb0;
            g_scan[ob + 32] = q1 + (p1 - mu) * rs * tg1 + tb1;

            if (s + 1 < S_) {
                float P0 = kk0[bw]*kk0[0] + kk1[bw]*kk1[0];
                float P1 = kk0[bw]*kk0[1] + kk1[bw]*kk1[1];
                float P2 = kk0[bw]*kk0[2] + kk1[bw]*kk1[2];
                float P3 = kk0[bw]*kk0[3] + kk1[bw]*kk1[3];
                bfly4(P0, P1, P2, P3);
                Mreg[0] = -LR * (P0 + 1.0f);
                Mreg[1] = -LR * (P1 + 1.0f);
                Mreg[2] = -LR * (P2 + 1.0f);
                Mreg[3] = -LR * (P3 + 1.0f);
                if (l == 0) {
                    Ms[bw][0] = Mreg[0]; Ms[bw][1] = Mreg[1];
                    Ms[bw][2] = Mreg[2]; Ms[bw][3] = Mreg[3];
                }
                size_t qb = (size_t)((s + 1) * B_ + bw) * E_ + hb + l;
                q0 = g_q[qb];
                q1 = g_q[qb + 32];
                if (s + 2 < S_) {
#pragma unroll
                    for (int b = 0; b < 4; b++) {
                        size_t kb = (size_t)((s + 2) * B_ + b) * E_ + hb + l;
                        kk0[b] = g_k[kb];
                        kk1[b] = g_k[kb + 32];
                    }
                }
            }
        }
    }
}

// ---------------------------------------------------------------------------
__global__ void __launch_bounds__(256)
post_kernel(const float* __restrict__ post_g, const float* __restrict__ post_b)
{
    __shared__ float red[8][2];
    const int row = blockIdx.x;
    const int b = row >> 11;
    const int s = row & 2047;
    const float* in = g_scan + (size_t)(s * B_ + b) * E_;
    const float* gp = g_gate + (size_t)row * E_;
    float* out = g_y + (size_t)row * E_;

    const int tid = threadIdx.x, warp = tid >> 5, lane = tid & 31;
    float vals[4];
    float sum = 0.f, sq = 0.f;
#pragma unroll
    for (int i = 0; i < 4; i++) {
        float x = in[tid + 256 * i];
        vals[i] = x; sum += x; sq += x * x;
    }
#pragma unroll
    for (int o = 16; o > 0; o >>= 1) {
        sum += __shfl_xor_sync(~0u, sum, o);
        sq  += __shfl_xor_sync(~0u, sq, o);
    }
    if (lane == 0) { red[warp][0] = sum; red[warp][1] = sq; }
    __syncthreads();
    float fs = 0.f, fq = 0.f;
#pragma unroll
    for (int w = 0; w < 8; w++) { fs += red[w][0]; fq += red[w][1]; }
    float mu = fs * (1.0f / 1024.0f);
    float rs = rsqrtf(fq * (1.0f / 1024.0f) - mu * mu + LN_EPS);

#pragma unroll
    for (int i = 0; i < 4; i++) {
        int e = tid + 256 * i;
        float xh = (vals[i] - mu) * rs * post_g[e] + post_b[e];
        float x = gp[e];
        float t = 0.7978845608028654f * (x + 0.044715f * x * x * x);
        float gelu = 0.5f * x * (1.0f + tanhf(t));
        out[e] = gelu * xh;
    }
}

// ---------------------------------------------------------------------------
extern "C" void kernel_launch(void* const* d_in, const int* in_sizes, int n_in,
                              void* d_out, int out_size)
{
    const float* x      = (const float*)d_in[0];
    const float* Wq     = (const float*)d_in[1];
    const float* Wk     = (const float*)d_in[2];
    const float* Wv     = (const float*)d_in[3];
    const float* Wo     = (const float*)d_in[4];
    const float* Wg     = (const float*)d_in[5];
    const float* fw_W   = (const float*)d_in[6];
    const float* fw_b   = (const float*)d_in[7];
    const float* fw_g   = (const float*)d_in[8];
    const float* fw_bl  = (const float*)d_in[9];
    const float* ttt_g  = (const float*)d_in[10];
    const float* ttt_b  = (const float*)d_in[11];
    const float* post_g = (const float*)d_in[12];
    const float* post_b = (const float*)d_in[13];

    gemm_kernel<<<dim3(32, 64), 256>>>(x, Wq, Wk, Wv, Wg, nullptr, E_, 1);
    scan_kernel<<<H_, 256>>>(fw_W, fw_b, fw_g, fw_bl, ttt_g, ttt_b);
    post_kernel<<<B_ * S_, 256>>>(post_g, post_b);
    gemm_kernel<<<dim3(8, 64), 256>>>(nullptr, Wo, Wo, Wo, Wo,
                                      (float*)d_out, E_, 0);
}

// round 6
// speedup vs baseline: 2.5266x; 1.1484x over previous
#include <cuda_runtime.h>
#include <cstdint>

#define B_ 4
#define S_ 2048
#define E_ 1024
#define H_ 16
#define D_ 64
#define LN_EPS 1e-5f
#define LR 0.1f
#define INV64 0.015625f
#define C_GRAD (2.0f / 4096.0f)   // 2/(B*H*D)

// ---------------- scratch (device globals; no allocation allowed) ----------
// q,k,v,scan stored as [s][b][e] with e = h*64+d
// gate, y stored as [b][s][e]
__device__ float g_q[S_ * B_ * E_];
__device__ float g_k[S_ * B_ * E_];
__device__ float g_v[S_ * B_ * E_];
__device__ float g_gate[B_ * S_ * E_];
__device__ float g_scan[S_ * B_ * E_];
__device__ float g_y[B_ * S_ * E_];
__device__ int   g_ready[16];          // qkv blocks done per 128-token chunk

// ---------------------------------------------------------------------------
__device__ __forceinline__ void bfly2(float& a, float& b)
{
#pragma unroll
    for (int o = 16; o > 0; o >>= 1) {
        a += __shfl_xor_sync(0xffffffffu, a, o);
        b += __shfl_xor_sync(0xffffffffu, b, o);
    }
}
__device__ __forceinline__ void bfly4(float& a, float& b, float& c, float& d)
{
#pragma unroll
    for (int o = 16; o > 0; o >>= 1) {
        a += __shfl_xor_sync(0xffffffffu, a, o);
        b += __shfl_xor_sync(0xffffffffu, b, o);
        c += __shfl_xor_sync(0xffffffffu, c, o);
        d += __shfl_xor_sync(0xffffffffu, d, o);
    }
}

__device__ __forceinline__ void wait_chunk(int c)
{
    if (*(volatile int*)&g_ready[c] < 96) {
        while (*(volatile int*)&g_ready[c] < 96) __nanosleep(256);
    }
    __threadfence();   // acquire: order subsequent loads after flag
}

#define BAR_A()    asm volatile("bar.sync 1, 128;" ::: "memory")
#define BAR_FULL() asm volatile("bar.sync 0, 256;" ::: "memory")

// ---------------------------------------------------------------------------
// Fused kernel: blocks 0-15 run the TTT scan (one head each); the remaining
// 2048 blocks run the qkvg projection GEMM, chunk-major so the scan can start
// consuming tokens while later chunks are still being produced.
// ---------------------------------------------------------------------------
__global__ void __launch_bounds__(256)
fused_kernel(const float* __restrict__ x,
             const float* __restrict__ Wq, const float* __restrict__ Wk,
             const float* __restrict__ Wv, const float* __restrict__ Wg,
             const float* __restrict__ fw_W, const float* __restrict__ fw_b,
             const float* __restrict__ fw_g, const float* __restrict__ fw_bl,
             const float* __restrict__ ttt_g, const float* __restrict__ ttt_b)
{
    const int tid = threadIdx.x;

    if (blockIdx.x >= 16) {
        // ==================== GEMM producer ====================
        __shared__ float As[2][8][128];
        __shared__ float Bs[2][8][128];

        int gid = blockIdx.x - 16;
        int bmp, bn;
        if (gid < 1536) { bmp = gid / 24; bn = gid % 24; }          // q,k,v
        else { int g2 = gid - 1536; bmp = g2 >> 3; bn = 24 + (g2 & 7); } // gate
        const int chunk = bmp >> 2;
        const int b     = bmp & 3;
        const int rowbase = b * 2048 + chunk * 128;
        const int nbase = bn * 128;
        const int p = nbase >> 10;
        const float* Bmat = (p == 0) ? Wq : (p == 1) ? Wk : (p == 2) ? Wv : Wg;
        const int frow = nbase & 1023;

        const int lm = tid >> 1;
        const int lk = (tid & 1) * 4;
        const float* Arow = x + (size_t)(rowbase + lm) * 1024 + lk;
        const float* Brow = Bmat + (size_t)(frow + lm) * 1024 + lk;

        float acc[8][8];
#pragma unroll
        for (int i = 0; i < 8; i++)
#pragma unroll
            for (int j = 0; j < 8; j++) acc[i][j] = 0.f;

        const int tm = (tid >> 4) * 8;
        const int tn = (tid & 15) * 8;

        {
            float4 a4 = *(const float4*)(Arow);
            float4 b4 = *(const float4*)(Brow);
            As[0][lk + 0][lm] = a4.x; As[0][lk + 1][lm] = a4.y;
            As[0][lk + 2][lm] = a4.z; As[0][lk + 3][lm] = a4.w;
            Bs[0][lk + 0][lm] = b4.x; Bs[0][lk + 1][lm] = b4.y;
            Bs[0][lk + 2][lm] = b4.z; Bs[0][lk + 3][lm] = b4.w;
        }
        __syncthreads();

        for (int t = 0; t < 128; t++) {
            const int cur = t & 1, nxt = cur ^ 1;
            float4 a4, b4;
            const bool more = (t + 1 < 128);
            if (more) {
                a4 = *(const float4*)(Arow + (t + 1) * 8);
                b4 = *(const float4*)(Brow + (t + 1) * 8);
            }
#pragma unroll
            for (int kk = 0; kk < 8; kk++) {
                float a[8], bb[8];
#pragma unroll
                for (int i = 0; i < 8; i++) a[i] = As[cur][kk][tm + i];
#pragma unroll
                for (int j = 0; j < 8; j++) bb[j] = Bs[cur][kk][tn + j];
#pragma unroll
                for (int i = 0; i < 8; i++)
#pragma unroll
                    for (int j = 0; j < 8; j++) acc[i][j] += a[i] * bb[j];
            }
            if (more) {
                As[nxt][lk + 0][lm] = a4.x; As[nxt][lk + 1][lm] = a4.y;
                As[nxt][lk + 2][lm] = a4.z; As[nxt][lk + 3][lm] = a4.w;
                Bs[nxt][lk + 0][lm] = b4.x; Bs[nxt][lk + 1][lm] = b4.y;
                Bs[nxt][lk + 2][lm] = b4.z; Bs[nxt][lk + 3][lm] = b4.w;
            }
            __syncthreads();
        }

        const int f = (nbase & 1023) + tn;
#pragma unroll
        for (int i = 0; i < 8; i++) {
            int s = chunk * 128 + tm + i;
            if (p == 3) {
                float* dst = g_gate + (size_t)(b * 2048 + s) * 1024 + f;
#pragma unroll
                for (int j = 0; j < 8; j++) dst[j] = acc[i][j];
            } else {
                float* dst = (p == 0 ? g_q : p == 1 ? g_k : g_v)
                             + (size_t)(s * B_ + b) * 1024 + f;
#pragma unroll
                for (int j = 0; j < 8; j++) dst[j] = acc[i][j];
            }
        }
        if (p < 3) {
            __threadfence();
            __syncthreads();
            if (tid == 0) atomicAdd(&g_ready[chunk], 1);
        }
        return;
    }

    // ==================== SCAN consumer ====================
    __shared__ __align__(16) float ks[2][B_][D_];
    __shared__ __align__(16) float ts[2][B_][D_];
    __shared__ __align__(16) float pt[2][B_][D_];
    __shared__ float d1h[B_][D_];
    __shared__ float d1x[2][B_][D_], d1p[2][B_][D_];
    __shared__ float d2h[B_][D_], d2x[B_][D_], d2p[B_][D_];
    __shared__ float z2s[B_][D_], dsum[B_][D_];
    __shared__ float Ms[B_][B_];

    const int h = blockIdx.x;
    const int l = tid & 31;
    const int hb = h * 64;

    if (tid < 128) {
        // ================= GROUP A =================
        const int aw   = tid >> 5;
        const int ecol = tid & 63;
        const int rgrp = tid >> 6;
        const int lb   = tid >> 6;
        const int le   = tid & 63;

        float Wreg[32];
#pragma unroll
        for (int j = 0; j < 32; j++)
            Wreg[j] = fw_W[h * 4096 + (rgrp * 32 + j) * 64 + ecol];

        float bias0 = fw_b[hb + l],  bias1 = fw_b[hb + l + 32];
        float g0    = fw_g[hb + l],  g1    = fw_g[hb + l + 32];
        float bl0   = fw_bl[hb + l], bl1   = fw_bl[hb + l + 32];

        wait_chunk(0);
        float kf0 = g_k[(size_t)lb * E_ + hb + le];
        float kf1 = g_k[(size_t)(lb + 2) * E_ + hb + le];
        float vf0 = g_v[(size_t)lb * E_ + hb + le];
        float vf1 = g_v[(size_t)(lb + 2) * E_ + hb + le];

        for (int s = 0; s < S_; s++) {
            const int par = s & 1;
            ks[par][lb][le]     = kf0;
            ks[par][lb + 2][le] = kf1;
            ts[par][lb][le]     = vf0 - kf0;
            ts[par][lb + 2][le] = vf1 - kf1;
            BAR_A();

            if (s + 1 < S_) {
                if (((s + 1) & 127) == 0) wait_chunk((s + 1) >> 7);
                size_t nb = (size_t)((s + 1) * B_ + lb) * E_ + hb + le;
                kf0 = g_k[nb]; kf1 = g_k[nb + 2 * E_];
                vf0 = g_v[nb]; vf1 = g_v[nb + 2 * E_];
            }

            // ---- matvec partials ----
            const float4* k40 = (const float4*)&ks[par][0][rgrp * 32];
            const float4* k41 = (const float4*)&ks[par][1][rgrp * 32];
            const float4* k42 = (const float4*)&ks[par][2][rgrp * 32];
            const float4* k43 = (const float4*)&ks[par][3][rgrp * 32];
            float a0 = 0.f, a1 = 0.f, a2 = 0.f, a3 = 0.f;
#pragma unroll
            for (int i = 0; i < 8; i++) {
                float4 c0 = k40[i], c1 = k41[i], c2 = k42[i], c3 = k43[i];
                float w0 = Wreg[4*i], w1 = Wreg[4*i+1], w2 = Wreg[4*i+2], w3 = Wreg[4*i+3];
                a0 += c0.x*w0 + c0.y*w1 + c0.z*w2 + c0.w*w3;
                a1 += c1.x*w0 + c1.y*w1 + c1.z*w2 + c1.w*w3;
                a2 += c2.x*w0 + c2.y*w1 + c2.z*w2 + c2.w*w3;
                a3 += c3.x*w0 + c3.y*w1 + c3.z*w2 + c3.w*w3;
            }
            pt[rgrp][0][ecol] = a0;
            pt[rgrp][1][ecol] = a1;
            pt[rgrp][2][ecol] = a2;
            pt[rgrp][3][ecol] = a3;
            BAR_A();

            // ---- combine + LN1 ----
            float z0 = bias0 + pt[0][aw][l]      + pt[1][aw][l];
            float z1 = bias1 + pt[0][aw][l + 32] + pt[1][aw][l + 32];
            float sum = z0 + z1, sq = z0 * z0 + z1 * z1;
            bfly2(sum, sq);
            float mu   = sum * INV64;
            float rstd = rsqrtf(sq * INV64 - mu * mu + LN_EPS);
            float xh0 = (z0 - mu) * rstd, xh1 = (z1 - mu) * rstd;

            // ---- bwd1 ----
            float t0 = ts[par][aw][l], t1 = ts[par][aw][l + 32];
            float p0 = xh0 * g0 + bl0, p1 = xh1 * g1 + bl1;
            float dp0 = C_GRAD * (p0 - t0), dp1 = C_GRAD * (p1 - t1);
            float dx0 = dp0 * g0, dx1 = dp1 * g1;
            float S1 = dx0 + dx1, S2 = dx0 * xh0 + dx1 * xh1;
            bfly2(S1, S2);
            float dh0 = rstd * (dx0 - (S1 + xh0 * S2) * INV64);
            float dh1 = rstd * (dx1 - (S1 + xh1 * S2) * INV64);
            d1h[aw][l]          = dh0;
            d1h[aw][l + 32]     = dh1;
            d1x[par][aw][l]      = dp0 * xh0;
            d1x[par][aw][l + 32] = dp1 * xh1;
            d1p[par][aw][l]      = dp0;
            d1p[par][aw][l + 32] = dp1;
            BAR_FULL();                                   // A3

            // ---- param update 1 (g2, bl2) ----
            float sx0 = d1x[par][0][l] + d1x[par][1][l] + d1x[par][2][l] + d1x[par][3][l];
            float sx1 = d1x[par][0][l+32] + d1x[par][1][l+32] + d1x[par][2][l+32] + d1x[par][3][l+32];
            float sp0 = d1p[par][0][l] + d1p[par][1][l] + d1p[par][2][l] + d1p[par][3][l];
            float sp1 = d1p[par][0][l+32] + d1p[par][1][l+32] + d1p[par][2][l+32] + d1p[par][3][l+32];
            g0 -= LR * sx0; g1 -= LR * sx1;
            bl0 -= LR * sp0; bl1 -= LR * sp1;

            // ---- corr2 ----
            float m0 = Ms[aw][0], m1 = Ms[aw][1], m2 = Ms[aw][2], m3 = Ms[aw][3];
            z0 += m0 * d1h[0][l] + m1 * d1h[1][l] + m2 * d1h[2][l] + m3 * d1h[3][l];
            z1 += m0 * d1h[0][l+32] + m1 * d1h[1][l+32] + m2 * d1h[2][l+32] + m3 * d1h[3][l+32];

            // ---- LN2 ----
            sum = z0 + z1; sq = z0 * z0 + z1 * z1;
            bfly2(sum, sq);
            mu   = sum * INV64;
            rstd = rsqrtf(sq * INV64 - mu * mu + LN_EPS);
            xh0 = (z0 - mu) * rstd; xh1 = (z1 - mu) * rstd;

            // ---- bwd2 ----
            p0 = xh0 * g0 + bl0; p1 = xh1 * g1 + bl1;
            dp0 = C_GRAD * (p0 - t0); dp1 = C_GRAD * (p1 - t1);
            dx0 = dp0 * g0; dx1 = dp1 * g1;
            S1 = dx0 + dx1; S2 = dx0 * xh0 + dx1 * xh1;
            bfly2(S1, S2);
            float e0 = rstd * (dx0 - (S1 + xh0 * S2) * INV64);
            float e1 = rstd * (dx1 - (S1 + xh1 * S2) * INV64);

            // ---- share2 ----
            z2s[aw][l]       = z0;   z2s[aw][l + 32]  = z1;
            d2h[aw][l]       = e0;   d2h[aw][l + 32]  = e1;
            d2x[aw][l]       = dp0 * xh0; d2x[aw][l + 32] = dp1 * xh1;
            d2p[aw][l]       = dp0;  d2p[aw][l + 32]  = dp1;
            dsum[aw][l]      = dh0 + e0;
            dsum[aw][l + 32] = dh1 + e1;
            BAR_FULL();                                   // S3

            // ---- param update 2 ----
            sx0 = d2x[0][l] + d2x[1][l] + d2x[2][l] + d2x[3][l];
            sx1 = d2x[0][l+32] + d2x[1][l+32] + d2x[2][l+32] + d2x[3][l+32];
            sp0 = d2p[0][l] + d2p[1][l] + d2p[2][l] + d2p[3][l];
            sp1 = d2p[0][l+32] + d2p[1][l+32] + d2p[2][l+32] + d2p[3][l+32];
            g0 -= LR * sx0; g1 -= LR * sx1;
            bl0 -= LR * sp0; bl1 -= LR * sp1;
            bias0 -= LR * (dsum[0][l] + dsum[1][l] + dsum[2][l] + dsum[3][l]);
            bias1 -= LR * (dsum[0][l+32] + dsum[1][l+32] + dsum[2][l+32] + dsum[3][l+32]);

            // ---- W update ----
            float ds0 = LR * dsum[0][ecol];
            float ds1 = LR * dsum[1][ecol];
            float ds2 = LR * dsum[2][ecol];
            float ds3 = LR * dsum[3][ecol];
#pragma unroll
            for (int i = 0; i < 8; i++) {
                float4 c0 = k40[i], c1 = k41[i], c2 = k42[i], c3 = k43[i];
                Wreg[4*i]   -= c0.x*ds0 + c1.x*ds1 + c2.x*ds2 + c3.x*ds3;
                Wreg[4*i+1] -= c0.y*ds0 + c1.y*ds1 + c2.y*ds2 + c3.y*ds3;
                Wreg[4*i+2] -= c0.z*ds0 + c1.z*ds1 + c2.z*ds2 + c3.z*ds3;
                Wreg[4*i+3] -= c0.w*ds0 + c1.w*ds1 + c2.w*ds2 + c3.w*ds3;
            }
        }
    } else {
        // ================= GROUP B =================
        const int bw = (tid >> 5) - 4;

        float g0  = fw_g[hb + l],  g1  = fw_g[hb + l + 32];
        float bl0 = fw_bl[hb + l], bl1 = fw_bl[hb + l + 32];
        float tg0 = ttt_g[hb + l], tg1 = ttt_g[hb + l + 32];
        float tb0 = ttt_b[hb + l], tb1 = ttt_b[hb + l + 32];

        wait_chunk(0);
        float kk0[4], kk1[4];
#pragma unroll
        for (int b = 0; b < 4; b++) {
            kk0[b] = g_k[(size_t)b * E_ + hb + l];
            kk1[b] = g_k[(size_t)b * E_ + hb + l + 32];
        }
        float Mreg[4];
        {
            float P0 = kk0[bw]*kk0[0] + kk1[bw]*kk1[0];
            float P1 = kk0[bw]*kk0[1] + kk1[bw]*kk1[1];
            float P2 = kk0[bw]*kk0[2] + kk1[bw]*kk1[2];
            float P3 = kk0[bw]*kk0[3] + kk1[bw]*kk1[3];
            bfly4(P0, P1, P2, P3);
            Mreg[0] = -LR * (P0 + 1.0f);
            Mreg[1] = -LR * (P1 + 1.0f);
            Mreg[2] = -LR * (P2 + 1.0f);
            Mreg[3] = -LR * (P3 + 1.0f);
            if (l == 0) {
                Ms[bw][0] = Mreg[0]; Ms[bw][1] = Mreg[1];
                Ms[bw][2] = Mreg[2]; Ms[bw][3] = Mreg[3];
            }
        }
        float q0 = g_q[(size_t)bw * E_ + hb + l];
        float q1 = g_q[(size_t)bw * E_ + hb + l + 32];
#pragma unroll
        for (int b = 0; b < 4; b++) {
            kk0[b] = g_k[(size_t)(1 * B_ + b) * E_ + hb + l];
            kk1[b] = g_k[(size_t)(1 * B_ + b) * E_ + hb + l + 32];
        }

        for (int s = 0; s < S_; s++) {
            BAR_FULL();                                   // A3
            BAR_FULL();                                   // S3
            const int par = s & 1;

            // ---- combined param update ----
            float sx0 = 0.f, sx1 = 0.f, sp0 = 0.f, sp1 = 0.f;
#pragma unroll
            for (int b = 0; b < 4; b++) {
                sx0 += d1x[par][b][l]      + d2x[b][l];
                sx1 += d1x[par][b][l + 32] + d2x[b][l + 32];
                sp0 += d1p[par][b][l]      + d2p[b][l];
                sp1 += d1p[par][b][l + 32] + d2p[b][l + 32];
            }
            g0 -= LR * sx0; g1 -= LR * sx1;
            bl0 -= LR * sp0; bl1 -= LR * sp1;

            // ---- corr3 ----
            float z0 = z2s[bw][l]
                     + Mreg[0]*d2h[0][l] + Mreg[1]*d2h[1][l]
                     + Mreg[2]*d2h[2][l] + Mreg[3]*d2h[3][l];
            float z1 = z2s[bw][l + 32]
                     + Mreg[0]*d2h[0][l+32] + Mreg[1]*d2h[1][l+32]
                     + Mreg[2]*d2h[2][l+32] + Mreg[3]*d2h[3][l+32];

            // ---- LN3 ----
            float sum = z0 + z1, sq = z0 * z0 + z1 * z1;
            bfly2(sum, sq);
            float mu = sum * INV64;
            float rs = rsqrtf(sq * INV64 - mu * mu + LN_EPS);
            float p0 = (z0 - mu) * rs * g0 + bl0;
            float p1 = (z1 - mu) * rs * g1 + bl1;

            // ---- LN4 + add q + store ----
            sum = p0 + p1; sq = p0 * p0 + p1 * p1;
            bfly2(sum, sq);
            mu = sum * INV64;
            rs = rsqrtf(sq * INV64 - mu * mu + LN_EPS);
            size_t ob = (size_t)(s * B_ + bw) * E_ + hb + l;
            g_scan[ob]      = q0 + (p0 - mu) * rs * tg0 + tb0;
            g_scan[ob + 32] = q1 + (p1 - mu) * rs * tg1 + tb1;

            if (s + 1 < S_) {
                float P0 = kk0[bw]*kk0[0] + kk1[bw]*kk1[0];
                float P1 = kk0[bw]*kk0[1] + kk1[bw]*kk1[1];
                float P2 = kk0[bw]*kk0[2] + kk1[bw]*kk1[2];
                float P3 = kk0[bw]*kk0[3] + kk1[bw]*kk1[3];
                bfly4(P0, P1, P2, P3);
                Mreg[0] = -LR * (P0 + 1.0f);
                Mreg[1] = -LR * (P1 + 1.0f);
                Mreg[2] = -LR * (P2 + 1.0f);
                Mreg[3] = -LR * (P3 + 1.0f);
                if (l == 0) {
                    Ms[bw][0] = Mreg[0]; Ms[bw][1] = Mreg[1];
                    Ms[bw][2] = Mreg[2]; Ms[bw][3] = Mreg[3];
                }
                size_t qb = (size_t)((s + 1) * B_ + bw) * E_ + hb + l;
                q0 = g_q[qb];
                q1 = g_q[qb + 32];
                if (s + 2 < S_) {
                    if (((s + 2) & 127) == 0) wait_chunk((s + 2) >> 7);
#pragma unroll
                    for (int b = 0; b < 4; b++) {
                        size_t kb = (size_t)((s + 2) * B_ + b) * E_ + hb + l;
                        kk0[b] = g_k[kb];
                        kk1[b] = g_k[kb + 32];
                    }
                }
            }
        }
    }
}

// ---------------------------------------------------------------------------
// Post: per (b,s) row — LN over E, *post_g+post_b, * gelu(gate_pre) -> g_y
// Also resets g_ready for the next graph replay.
// ---------------------------------------------------------------------------
__global__ void __launch_bounds__(256)
post_kernel(const float* __restrict__ post_g, const float* __restrict__ post_b)
{
    __shared__ float red[8][2];
    const int row = blockIdx.x;
    const int b = row >> 11;
    const int s = row & 2047;
    const int tid = threadIdx.x, warp = tid >> 5, lane = tid & 31;

    if (row == 0 && tid < 16) g_ready[tid] = 0;

    const float* in = g_scan + (size_t)(s * B_ + b) * E_;
    const float* gp = g_gate + (size_t)row * E_;
    float* out = g_y + (size_t)row * E_;

    float vals[4];
    float sum = 0.f, sq = 0.f;
#pragma unroll
    for (int i = 0; i < 4; i++) {
        float x = in[tid + 256 * i];
        vals[i] = x; sum += x; sq += x * x;
    }
#pragma unroll
    for (int o = 16; o > 0; o >>= 1) {
        sum += __shfl_xor_sync(~0u, sum, o);
        sq  += __shfl_xor_sync(~0u, sq, o);
    }
    if (lane == 0) { red[warp][0] = sum; red[warp][1] = sq; }
    __syncthreads();
    float fs = 0.f, fq = 0.f;
#pragma unroll
    for (int w = 0; w < 8; w++) { fs += red[w][0]; fq += red[w][1]; }
    float mu = fs * (1.0f / 1024.0f);
    float rs = rsqrtf(fq * (1.0f / 1024.0f) - mu * mu + LN_EPS);

#pragma unroll
    for (int i = 0; i < 4; i++) {
        int e = tid + 256 * i;
        float xh = (vals[i] - mu) * rs * post_g[e] + post_b[e];
        float x = gp[e];
        float t = 0.7978845608028654f * (x + 0.044715f * x * x * x);
        float gelu = 0.5f * x * (1.0f + tanhf(t));
        out[e] = gelu * xh;
    }
}

// ---------------------------------------------------------------------------
// Output projection: d_out[m,n] = sum_k g_y[m,k] * Wo[n,k]
// ---------------------------------------------------------------------------
__global__ void __launch_bounds__(256)
gemm2_kernel(const float* __restrict__ Wo, float* __restrict__ C)
{
    __shared__ float As[2][8][128];
    __shared__ float Bs[2][8][128];

    const int tid = threadIdx.x;
    const int bm = blockIdx.y, bn = blockIdx.x;
    const int nbase = bn * 128;

    const int lm = tid >> 1;
    const int lk = (tid & 1) * 4;
    const float* Arow = g_y + (size_t)(bm * 128 + lm) * 1024 + lk;
    const float* Brow = Wo + (size_t)(nbase + lm) * 1024 + lk;

    float acc[8][8];
#pragma unroll
    for (int i = 0; i < 8; i++)
#pragma unroll
        for (int j = 0; j < 8; j++) acc[i][j] = 0.f;

    const int tm = (tid >> 4) * 8;
    const int tn = (tid & 15) * 8;

    {
        float4 a4 = *(const float4*)(Arow);
        float4 b4 = *(const float4*)(Brow);
        As[0][lk + 0][lm] = a4.x; As[0][lk + 1][lm] = a4.y;
        As[0][lk + 2][lm] = a4.z; As[0][lk + 3][lm] = a4.w;
        Bs[0][lk + 0][lm] = b4.x; Bs[0][lk + 1][lm] = b4.y;
        Bs[0][lk + 2][lm] = b4.z; Bs[0][lk + 3][lm] = b4.w;
    }
    __syncthreads();

    for (int t = 0; t < 128; t++) {
        const int cur = t & 1, nxt = cur ^ 1;
        float4 a4, b4;
        const bool more = (t + 1 < 128);
        if (more) {
            a4 = *(const float4*)(Arow + (t + 1) * 8);
            b4 = *(const float4*)(Brow + (t + 1) * 8);
        }
#pragma unroll
        for (int kk = 0; kk < 8; kk++) {
            float a[8], bb[8];
#pragma unroll
            for (int i = 0; i < 8; i++) a[i] = As[cur][kk][tm + i];
#pragma unroll
            for (int j = 0; j < 8; j++) bb[j] = Bs[cur][kk][tn + j];
#pragma unroll
            for (int i = 0; i < 8; i++)
#pragma unroll
                for (int j = 0; j < 8; j++) acc[i][j] += a[i] * bb[j];
        }
        if (more) {
            As[nxt][lk + 0][lm] = a4.x; As[nxt][lk + 1][lm] = a4.y;
            As[nxt][lk + 2][lm] = a4.z; As[nxt][lk + 3][lm] = a4.w;
            Bs[nxt][lk + 0][lm] = b4.x; Bs[nxt][lk + 1][lm] = b4.y;
            Bs[nxt][lk + 2][lm] = b4.z; Bs[nxt][lk + 3][lm] = b4.w;
        }
        __syncthreads();
    }

#pragma unroll
    for (int i = 0; i < 8; i++) {
        int m = bm * 128 + tm + i;
        float* crow = C + (size_t)m * 1024 + nbase + tn;
#pragma unroll
        for (int j = 0; j < 8; j++) crow[j] = acc[i][j];
    }
}

// ---------------------------------------------------------------------------
extern "C" void kernel_launch(void* const* d_in, const int* in_sizes, int n_in,
                              void* d_out, int out_size)
{
    const float* x      = (const float*)d_in[0];
    const float* Wq     = (const float*)d_in[1];
    const float* Wk     = (const float*)d_in[2];
    const float* Wv     = (const float*)d_in[3];
    const float* Wo     = (const float*)d_in[4];
    const float* Wg     = (const float*)d_in[5];
    const float* fw_W   = (const float*)d_in[6];
    const float* fw_b   = (const float*)d_in[7];
    const float* fw_g   = (const float*)d_in[8];
    const float* fw_bl  = (const float*)d_in[9];
    const float* ttt_g  = (const float*)d_in[10];
    const float* ttt_b  = (const float*)d_in[11];
    const float* post_g = (const float*)d_in[12];
    const float* post_b = (const float*)d_in[13];

    // fused: 16 scan blocks + 2048 projection-GEMM blocks, pipelined by chunk
    fused_kernel<<<16 + 2048, 256>>>(x, Wq, Wk, Wv, Wg,
                                     fw_W, fw_b, fw_g, fw_bl, ttt_g, ttt_b);
    post_kernel<<<B_ * S_, 256>>>(post_g, post_b);
    gemm2_kernel<<<dim3(8, 64), 256>>>(Wo, (float*)d_out);
}

// round 8
// speedup vs baseline: 3.3534x; 1.3272x over previous
#include <cuda_runtime.h>
#include <cstdint>

#define B_ 4
#define S_ 2048
#define E_ 1024
#define H_ 16
#define D_ 64
#define LN_EPS 1e-5f
#define LR 0.1f
#define INV64 0.015625f
#define C_GRAD (2.0f / 4096.0f)   // 2/(B*H*D)

#define N_WORKERS 296
#define N_TILES 2048

// ---------------- scratch (device globals; no allocation allowed) ----------
__device__ float g_q[S_ * B_ * E_];
__device__ float g_k[S_ * B_ * E_];
__device__ float g_v[S_ * B_ * E_];
__device__ float g_gate[B_ * S_ * E_];
__device__ float g_scan[S_ * B_ * E_];
__device__ float g_y[B_ * S_ * E_];
__device__ int   g_ready[16];      // qkv tiles done per 128-token chunk
__device__ int   g_tile;           // gemm tile queue head
__device__ int   g_nscan;          // scan blocks that published their smid
__device__ int   g_smids[16];      // smids hosting scan blocks

// ---------------------------------------------------------------------------
__device__ __forceinline__ void bfly2(float& a, float& b)
{
#pragma unroll
    for (int o = 16; o > 0; o >>= 1) {
        a += __shfl_xor_sync(0xffffffffu, a, o);
        b += __shfl_xor_sync(0xffffffffu, b, o);
    }
}
__device__ __forceinline__ void bfly4(float& a, float& b, float& c, float& d)
{
#pragma unroll
    for (int o = 16; o > 0; o >>= 1) {
        a += __shfl_xor_sync(0xffffffffu, a, o);
        b += __shfl_xor_sync(0xffffffffu, b, o);
        c += __shfl_xor_sync(0xffffffffu, c, o);
        d += __shfl_xor_sync(0xffffffffu, d, o);
    }
}

__device__ __forceinline__ void wait_chunk(int c)
{
    if (*(volatile int*)&g_ready[c] < 96) {
        while (*(volatile int*)&g_ready[c] < 96) __nanosleep(256);
    }
    __threadfence();   // acquire
}

__device__ __forceinline__ unsigned my_smid()
{
    unsigned s;
    asm("mov.u32 %0, %%smid;" : "=r"(s));
    return s;
}

#define BAR_A()    asm volatile("bar.sync 1, 128;" ::: "memory")
#define BAR_FULL() asm volatile("bar.sync 0, 256;" ::: "memory")

// ---------------------------------------------------------------------------
// Fused: blocks 0-15 = TTT scan (one head each, publish smid).
// Blocks 16.. = persistent GEMM workers over a tile queue; workers landing on
// a scan SM exit immediately -> scan SMs stay exclusive.
// ---------------------------------------------------------------------------
__global__ void __launch_bounds__(256)
fused_kernel(const float* __restrict__ x,
             const float* __restrict__ Wq, const float* __restrict__ Wk,
             const float* __restrict__ Wv, const float* __restrict__ Wg,
             const float* __restrict__ fw_W, const float* __restrict__ fw_b,
             const float* __restrict__ fw_g, const float* __restrict__ fw_bl,
             const float* __restrict__ ttt_g, const float* __restrict__ ttt_b)
{
    const int tid = threadIdx.x;

    if (blockIdx.x >= 16) {
        // ==================== persistent GEMM worker ====================
        __shared__ float As[2][8][128];
        __shared__ float Bs[2][8][128];
        __shared__ int s_flag, s_tile;

        if (tid == 0) {
            unsigned smid = my_smid();
            int it = 0;
            while (*(volatile int*)&g_nscan < 16 && it < 50000) {
                __nanosleep(128); it++;
            }
            __threadfence();
            int excl = 0;
            if (*(volatile int*)&g_nscan >= 16) {
#pragma unroll
                for (int i = 0; i < 16; i++)
                    if (g_smids[i] == (int)smid) excl = 1;
            }
            s_flag = excl;
        }
        __syncthreads();
        if (s_flag) return;   // this SM hosts a scan block — vacate it

        const int lm = tid >> 1;
        const int lk = (tid & 1) * 4;
        const int tm = (tid >> 4) * 8;
        const int tn = (tid & 15) * 8;

        for (;;) {
            if (tid == 0) s_tile = atomicAdd(&g_tile, 1);
            __syncthreads();
            const int gid = s_tile;
            if (gid >= N_TILES) break;

            int bmp, bn;
            if (gid < 1536) { bmp = gid / 24; bn = gid % 24; }            // q,k,v
            else { int g2 = gid - 1536; bmp = g2 >> 3; bn = 24 + (g2 & 7); } // gate
            const int chunk = bmp >> 2;
            const int b     = bmp & 3;
            const int rowbase = b * 2048 + chunk * 128;
            const int nbase = bn * 128;
            const int p = nbase >> 10;
            const float* Bmat = (p == 0) ? Wq : (p == 1) ? Wk : (p == 2) ? Wv : Wg;
            const int frow = nbase & 1023;

            const float* Arow = x + (size_t)(rowbase + lm) * 1024 + lk;
            const float* Brow = Bmat + (size_t)(frow + lm) * 1024 + lk;

            float acc[8][8];
#pragma unroll
            for (int i = 0; i < 8; i++)
#pragma unroll
                for (int j = 0; j < 8; j++) acc[i][j] = 0.f;

            {
                float4 a4 = *(const float4*)(Arow);
                float4 b4 = *(const float4*)(Brow);
                As[0][lk + 0][lm] = a4.x; As[0][lk + 1][lm] = a4.y;
                As[0][lk + 2][lm] = a4.z; As[0][lk + 3][lm] = a4.w;
                Bs[0][lk + 0][lm] = b4.x; Bs[0][lk + 1][lm] = b4.y;
                Bs[0][lk + 2][lm] = b4.z; Bs[0][lk + 3][lm] = b4.w;
            }
            __syncthreads();

            for (int t = 0; t < 128; t++) {
                const int cur = t & 1, nxt = cur ^ 1;
                float4 a4, b4;
                const bool more = (t + 1 < 128);
                if (more) {
                    a4 = *(const float4*)(Arow + (t + 1) * 8);
                    b4 = *(const float4*)(Brow + (t + 1) * 8);
                }
#pragma unroll
                for (int kk = 0; kk < 8; kk++) {
                    float a[8], bb[8];
#pragma unroll
                    for (int i = 0; i < 8; i++) a[i] = As[cur][kk][tm + i];
#pragma unroll
                    for (int j = 0; j < 8; j++) bb[j] = Bs[cur][kk][tn + j];
#pragma unroll
                    for (int i = 0; i < 8; i++)
#pragma unroll
                        for (int j = 0; j < 8; j++) acc[i][j] += a[i] * bb[j];
                }
                if (more) {
                    As[nxt][lk + 0][lm] = a4.x; As[nxt][lk + 1][lm] = a4.y;
                    As[nxt][lk + 2][lm] = a4.z; As[nxt][lk + 3][lm] = a4.w;
                    Bs[nxt][lk + 0][lm] = b4.x; Bs[nxt][lk + 1][lm] = b4.y;
                    Bs[nxt][lk + 2][lm] = b4.z; Bs[nxt][lk + 3][lm] = b4.w;
                }
                __syncthreads();
            }

            const int f = (nbase & 1023) + tn;
#pragma unroll
            for (int i = 0; i < 8; i++) {
                int s = chunk * 128 + tm + i;
                if (p == 3) {
                    float* dst = g_gate + (size_t)(b * 2048 + s) * 1024 + f;
#pragma unroll
                    for (int j = 0; j < 8; j++) dst[j] = acc[i][j];
                } else {
                    float* dst = (p == 0 ? g_q : p == 1 ? g_k : g_v)
                                 + (size_t)(s * B_ + b) * 1024 + f;
#pragma unroll
                    for (int j = 0; j < 8; j++) dst[j] = acc[i][j];
                }
            }
            __threadfence();
            __syncthreads();     // all stores done; also guards s_tile rewrite
            if (p < 3 && tid == 0) atomicAdd(&g_ready[chunk], 1);
        }
        return;
    }

    // ==================== SCAN (blocks 0-15) ====================
    __shared__ __align__(16) float ks[2][B_][D_];
    __shared__ __align__(16) float ts[2][B_][D_];
    __shared__ __align__(16) float pt[2][B_][D_];
    __shared__ float d1h[B_][D_];
    __shared__ float d1x[2][B_][D_], d1p[2][B_][D_];
    __shared__ float d2h[B_][D_], d2x[B_][D_], d2p[B_][D_];
    __shared__ float z2s[B_][D_], dsum[B_][D_];
    __shared__ float Ms[B_][B_];

    const int h = blockIdx.x;
    const int l = tid & 31;
    const int hb = h * 64;

    if (tid == 0) {
        g_smids[h] = (int)my_smid();
        __threadfence();
        atomicAdd(&g_nscan, 1);
    }

    if (tid < 128) {
        // ================= GROUP A =================
        const int aw   = tid >> 5;
        const int ecol = tid & 63;
        const int rgrp = tid >> 6;
        const int lb   = tid >> 6;
        const int le   = tid & 63;

        float Wreg[32];
#pragma unroll
        for (int j = 0; j < 32; j++)
            Wreg[j] = fw_W[h * 4096 + (rgrp * 32 + j) * 64 + ecol];

        float bias0 = fw_b[hb + l],  bias1 = fw_b[hb + l + 32];
        float g0    = fw_g[hb + l],  g1    = fw_g[hb + l + 32];
        float bl0   = fw_bl[hb + l], bl1   = fw_bl[hb + l + 32];

        wait_chunk(0);
        float kf0 = g_k[(size_t)lb * E_ + hb + le];
        float kf1 = g_k[(size_t)(lb + 2) * E_ + hb + le];
        float vf0 = g_v[(size_t)lb * E_ + hb + le];
        float vf1 = g_v[(size_t)(lb + 2) * E_ + hb + le];

        for (int s = 0; s < S_; s++) {
            const int par = s & 1;
            ks[par][lb][le]     = kf0;
            ks[par][lb + 2][le] = kf1;
            ts[par][lb][le]     = vf0 - kf0;
            ts[par][lb + 2][le] = vf1 - kf1;
            BAR_A();

            if (s + 1 < S_) {
                if (((s + 1) & 127) == 0) wait_chunk((s + 1) >> 7);
                size_t nb = (size_t)((s + 1) * B_ + lb) * E_ + hb + le;
                kf0 = g_k[nb]; kf1 = g_k[nb + 2 * E_];
                vf0 = g_v[nb]; vf1 = g_v[nb + 2 * E_];
            }

            // ---- matvec partials ----
            const float4* k40 = (const float4*)&ks[par][0][rgrp * 32];
            const float4* k41 = (const float4*)&ks[par][1][rgrp * 32];
            const float4* k42 = (const float4*)&ks[par][2][rgrp * 32];
            const float4* k43 = (const float4*)&ks[par][3][rgrp * 32];
            float a0 = 0.f, a1 = 0.f, a2 = 0.f, a3 = 0.f;
#pragma unroll
            for (int i = 0; i < 8; i++) {
                float4 c0 = k40[i], c1 = k41[i], c2 = k42[i], c3 = k43[i];
                float w0 = Wreg[4*i], w1 = Wreg[4*i+1], w2 = Wreg[4*i+2], w3 = Wreg[4*i+3];
                a0 += c0.x*w0 + c0.y*w1 + c0.z*w2 + c0.w*w3;
                a1 += c1.x*w0 + c1.y*w1 + c1.z*w2 + c1.w*w3;
                a2 += c2.x*w0 + c2.y*w1 + c2.z*w2 + c2.w*w3;
                a3 += c3.x*w0 + c3.y*w1 + c3.z*w2 + c3.w*w3;
            }
            pt[rgrp][0][ecol] = a0;
            pt[rgrp][1][ecol] = a1;
            pt[rgrp][2][ecol] = a2;
            pt[rgrp][3][ecol] = a3;
            BAR_A();

            // ---- combine + LN1 ----
            float z0 = bias0 + pt[0][aw][l]      + pt[1][aw][l];
            float z1 = bias1 + pt[0][aw][l + 32] + pt[1][aw][l + 32];
            float sum = z0 + z1, sq = z0 * z0 + z1 * z1;
            bfly2(sum, sq);
            float mu   = sum * INV64;
            float rstd = rsqrtf(sq * INV64 - mu * mu + LN_EPS);
            float xh0 = (z0 - mu) * rstd, xh1 = (z1 - mu) * rstd;

            // ---- bwd1 ----
            float t0 = ts[par][aw][l], t1 = ts[par][aw][l + 32];
            float p0 = xh0 * g0 + bl0, p1 = xh1 * g1 + bl1;
            float dp0 = C_GRAD * (p0 - t0), dp1 = C_GRAD * (p1 - t1);
            float dx0 = dp0 * g0, dx1 = dp1 * g1;
            float S1 = dx0 + dx1, S2 = dx0 * xh0 + dx1 * xh1;
            bfly2(S1, S2);
            float dh0 = rstd * (dx0 - (S1 + xh0 * S2) * INV64);
            float dh1 = rstd * (dx1 - (S1 + xh1 * S2) * INV64);
            d1h[aw][l]          = dh0;
            d1h[aw][l + 32]     = dh1;
            d1x[par][aw][l]      = dp0 * xh0;
            d1x[par][aw][l + 32] = dp1 * xh1;
            d1p[par][aw][l]      = dp0;
            d1p[par][aw][l + 32] = dp1;
            BAR_FULL();                                   // A3

            // ---- param update 1 ----
            float sx0 = d1x[par][0][l] + d1x[par][1][l] + d1x[par][2][l] + d1x[par][3][l];
            float sx1 = d1x[par][0][l+32] + d1x[par][1][l+32] + d1x[par][2][l+32] + d1x[par][3][l+32];
            float sp0 = d1p[par][0][l] + d1p[par][1][l] + d1p[par][2][l] + d1p[par][3][l];
            float sp1 = d1p[par][0][l+32] + d1p[par][1][l+32] + d1p[par][2][l+32] + d1p[par][3][l+32];
            g0 -= LR * sx0; g1 -= LR * sx1;
            bl0 -= LR * sp0; bl1 -= LR * sp1;

            // ---- corr2 ----
            float m0 = Ms[aw][0], m1 = Ms[aw][1], m2 = Ms[aw][2], m3 = Ms[aw][3];
            z0 += m0 * d1h[0][l] + m1 * d1h[1][l] + m2 * d1h[2][l] + m3 * d1h[3][l];
            z1 += m0 * d1h[0][l+32] + m1 * d1h[1][l+32] + m2 * d1h[2][l+32] + m3 * d1h[3][l+32];

            // ---- LN2 ----
            sum = z0 + z1; sq = z0 * z0 + z1 * z1;
            bfly2(sum, sq);
            mu   = sum * INV64;
            rstd = rsqrtf(sq * INV64 - mu * mu + LN_EPS);
            xh0 = (z0 - mu) * rstd; xh1 = (z1 - mu) * rstd;

            // ---- bwd2 ----
            p0 = xh0 * g0 + bl0; p1 = xh1 * g1 + bl1;
            dp0 = C_GRAD * (p0 - t0); dp1 = C_GRAD * (p1 - t1);
            dx0 = dp0 * g0; dx1 = dp1 * g1;
            S1 = dx0 + dx1; S2 = dx0 * xh0 + dx1 * xh1;
            bfly2(S1, S2);
            float e0 = rstd * (dx0 - (S1 + xh0 * S2) * INV64);
            float e1 = rstd * (dx1 - (S1 + xh1 * S2) * INV64);

            // ---- share2 ----
            z2s[aw][l]       = z0;   z2s[aw][l + 32]  = z1;
            d2h[aw][l]       = e0;   d2h[aw][l + 32]  = e1;
            d2x[aw][l]       = dp0 * xh0; d2x[aw][l + 32] = dp1 * xh1;
            d2p[aw][l]       = dp0;  d2p[aw][l + 32]  = dp1;
            dsum[aw][l]      = dh0 + e0;
            dsum[aw][l + 32] = dh1 + e1;
            BAR_FULL();                                   // S3

            // ---- param update 2 ----
            sx0 = d2x[0][l] + d2x[1][l] + d2x[2][l] + d2x[3][l];
            sx1 = d2x[0][l+32] + d2x[1][l+32] + d2x[2][l+32] + d2x[3][l+32];
            sp0 = d2p[0][l] + d2p[1][l] + d2p[2][l] + d2p[3][l];
            sp1 = d2p[0][l+32] + d2p[1][l+32] + d2p[2][l+32] + d2p[3][l+32];
            g0 -= LR * sx0; g1 -= LR * sx1;
            bl0 -= LR * sp0; bl1 -= LR * sp1;
            bias0 -= LR * (dsum[0][l] + dsum[1][l] + dsum[2][l] + dsum[3][l]);
            bias1 -= LR * (dsum[0][l+32] + dsum[1][l+32] + dsum[2][l+32] + dsum[3][l+32]);

            // ---- W update ----
            float ds0 = LR * dsum[0][ecol];
            float ds1 = LR * dsum[1][ecol];
            float ds2 = LR * dsum[2][ecol];
            float ds3 = LR * dsum[3][ecol];
#pragma unroll
            for (int i = 0; i < 8; i++) {
                float4 c0 = k40[i], c1 = k41[i], c2 = k42[i], c3 = k43[i];
                Wreg[4*i]   -= c0.x*ds0 + c1.x*ds1 + c2.x*ds2 + c3.x*ds3;
                Wreg[4*i+1] -= c0.y*ds0 + c1.y*ds1 + c2.y*ds2 + c3.y*ds3;
                Wreg[4*i+2] -= c0.z*ds0 + c1.z*ds1 + c2.z*ds2 + c3.z*ds3;
                Wreg[4*i+3] -= c0.w*ds0 + c1.w*ds1 + c2.w*ds2 + c3.w*ds3;
            }
        }
    } else {
        // ================= GROUP B =================
        const int bw = (tid >> 5) - 4;

        float g0  = fw_g[hb + l],  g1  = fw_g[hb + l + 32];
        float bl0 = fw_bl[hb + l], bl1 = fw_bl[hb + l + 32];
        float tg0 = ttt_g[hb + l], tg1 = ttt_g[hb + l + 32];
        float tb0 = ttt_b[hb + l], tb1 = ttt_b[hb + l + 32];

        wait_chunk(0);
        float kk0[4], kk1[4];
#pragma unroll
        for (int b = 0; b < 4; b++) {
            kk0[b] = g_k[(size_t)b * E_ + hb + l];
            kk1[b] = g_k[(size_t)b * E_ + hb + l + 32];
        }
        float Mreg[4];
        {
            float P0 = kk0[bw]*kk0[0] + kk1[bw]*kk1[0];
            float P1 = kk0[bw]*kk0[1] + kk1[bw]*kk1[1];
            float P2 = kk0[bw]*kk0[2] + kk1[bw]*kk1[2];
            float P3 = kk0[bw]*kk0[3] + kk1[bw]*kk1[3];
            bfly4(P0, P1, P2, P3);
            Mreg[0] = -LR * (P0 + 1.0f);
            Mreg[1] = -LR * (P1 + 1.0f);
            Mreg[2] = -LR * (P2 + 1.0f);
            Mreg[3] = -LR * (P3 + 1.0f);
            if (l == 0) {
                Ms[bw][0] = Mreg[0]; Ms[bw][1] = Mreg[1];
                Ms[bw][2] = Mreg[2]; Ms[bw][3] = Mreg[3];
            }
        }
        float q0 = g_q[(size_t)bw * E_ + hb + l];
        float q1 = g_q[(size_t)bw * E_ + hb + l + 32];
#pragma unroll
        for (int b = 0; b < 4; b++) {
            kk0[b] = g_k[(size_t)(1 * B_ + b) * E_ + hb + l];
            kk1[b] = g_k[(size_t)(1 * B_ + b) * E_ + hb + l + 32];
        }

        for (int s = 0; s < S_; s++) {
            BAR_FULL();                                   // A3
            BAR_FULL();                                   // S3
            const int par = s & 1;

            // ---- combined param update ----
            float sx0 = 0.f, sx1 = 0.f, sp0 = 0.f, sp1 = 0.f;
#pragma unroll
            for (int b = 0; b < 4; b++) {
                sx0 += d1x[par][b][l]      + d2x[b][l];
                sx1 += d1x[par][b][l + 32] + d2x[b][l + 32];
                sp0 += d1p[par][b][l]      + d2p[b][l];
                sp1 += d1p[par][b][l + 32] + d2p[b][l + 32];
            }
            g0 -= LR * sx0; g1 -= LR * sx1;
            bl0 -= LR * sp0; bl1 -= LR * sp1;

            // ---- corr3 ----
            float z0 = z2s[bw][l]
                     + Mreg[0]*d2h[0][l] + Mreg[1]*d2h[1][l]
                     + Mreg[2]*d2h[2][l] + Mreg[3]*d2h[3][l];
            float z1 = z2s[bw][l + 32]
                     + Mreg[0]*d2h[0][l+32] + Mreg[1]*d2h[1][l+32]
                     + Mreg[2]*d2h[2][l+32] + Mreg[3]*d2h[3][l+32];

            // ---- LN3 ----
            float sum = z0 + z1, sq = z0 * z0 + z1 * z1;
            bfly2(sum, sq);
            float mu = sum * INV64;
            float rs = rsqrtf(sq * INV64 - mu * mu + LN_EPS);
            float p0 = (z0 - mu) * rs * g0 + bl0;
            float p1 = (z1 - mu) * rs * g1 + bl1;

            // ---- LN4 + add q + store ----
            sum = p0 + p1; sq = p0 * p0 + p1 * p1;
            bfly2(sum, sq);
            mu = sum * INV64;
            rs = rsqrtf(sq * INV64 - mu * mu + LN_EPS);
            size_t ob = (size_t)(s * B_ + bw) * E_ + hb + l;
            g_scan[ob]      = q0 + (p0 - mu) * rs * tg0 + tb0;
            g_scan[ob + 32] = q1 + (p1 - mu) * rs * tg1 + tb1;

            if (s + 1 < S_) {
                float P0 = kk0[bw]*kk0[0] + kk1[bw]*kk1[0];
                float P1 = kk0[bw]*kk0[1] + kk1[bw]*kk1[1];
                float P2 = kk0[bw]*kk0[2] + kk1[bw]*kk1[2];
                float P3 = kk0[bw]*kk0[3] + kk1[bw]*kk1[3];
                bfly4(P0, P1, P2, P3);
                Mreg[0] = -LR * (P0 + 1.0f);
                Mreg[1] = -LR * (P1 + 1.0f);
                Mreg[2] = -LR * (P2 + 1.0f);
                Mreg[3] = -LR * (P3 + 1.0f);
                if (l == 0) {
                    Ms[bw][0] = Mreg[0]; Ms[bw][1] = Mreg[1];
                    Ms[bw][2] = Mreg[2]; Ms[bw][3] = Mreg[3];
                }
                size_t qb = (size_t)((s + 1) * B_ + bw) * E_ + hb + l;
                q0 = g_q[qb];
                q1 = g_q[qb + 32];
                if (s + 2 < S_) {
                    if (((s + 2) & 127) == 0) wait_chunk((s + 2) >> 7);
#pragma unroll
                    for (int b = 0; b < 4; b++) {
                        size_t kb = (size_t)((s + 2) * B_ + b) * E_ + hb + l;
                        kk0[b] = g_k[kb];
                        kk1[b] = g_k[kb + 32];
                    }
                }
            }
        }
    }
}

// ---------------------------------------------------------------------------
// Post: per (b,s) row — LN over E, *post_g+post_b, * gelu(gate_pre) -> g_y
// Also resets the queue/flag globals for the next graph replay.
// ---------------------------------------------------------------------------
__global__ void __launch_bounds__(256)
post_kernel(const float* __restrict__ post_g, const float* __restrict__ post_b)
{
    __shared__ float red[8][2];
    const int row = blockIdx.x;
    const int b = row >> 11;
    const int s = row & 2047;
    const int tid = threadIdx.x, warp = tid >> 5, lane = tid & 31;

    if (row == 0) {
        if (tid < 16) g_ready[tid] = 0;
        else if (tid == 16) { g_tile = 0; g_nscan = 0; }
    }

    const float* in = g_scan + (size_t)(s * B_ + b) * E_;
    const float* gp = g_gate + (size_t)row * E_;
    float* out = g_y + (size_t)row * E_;

    float vals[4];
    float sum = 0.f, sq = 0.f;
#pragma unroll
    for (int i = 0; i < 4; i++) {
        float x = in[tid + 256 * i];
        vals[i] = x; sum += x; sq += x * x;
    }
#pragma unroll
    for (int o = 16; o > 0; o >>= 1) {
        sum += __shfl_xor_sync(~0u, sum, o);
        sq  += __shfl_xor_sync(~0u, sq, o);
    }
    if (lane == 0) { red[warp][0] = sum; red[warp][1] = sq; }
    __syncthreads();
    float fs = 0.f, fq = 0.f;
#pragma unroll
    for (int w = 0; w < 8; w++) { fs += red[w][0]; fq += red[w][1]; }
    float mu = fs * (1.0f / 1024.0f);
    float rs = rsqrtf(fq * (1.0f / 1024.0f) - mu * mu + LN_EPS);

#pragma unroll
    for (int i = 0; i < 4; i++) {
        int e = tid + 256 * i;
        float xh = (vals[i] - mu) * rs * post_g[e] + post_b[e];
        float x = gp[e];
        float t = 0.7978845608028654f * (x + 0.044715f * x * x * x);
        float gelu = 0.5f * x * (1.0f + tanhf(t));
        out[e] = gelu * xh;
    }
}

// ---------------------------------------------------------------------------
// Output projection: d_out[m,n] = sum_k g_y[m,k] * Wo[n,k]
// ---------------------------------------------------------------------------
__global__ void __launch_bounds__(256)
gemm2_kernel(const float* __restrict__ Wo, float* __restrict__ C)
{
    __shared__ float As[2][8][128];
    __shared__ float Bs[2][8][128];

    const int tid = threadIdx.x;
    const int bm = blockIdx.y, bn = blockIdx.x;
    const int nbase = bn * 128;

    const int lm = tid >> 1;
    const int lk = (tid & 1) * 4;
    const float* Arow = g_y + (size_t)(bm * 128 + lm) * 1024 + lk;
    const float* Brow = Wo + (size_t)(nbase + lm) * 1024 + lk;

    float acc[8][8];
#pragma unroll
    for (int i = 0; i < 8; i++)
#pragma unroll
        for (int j = 0; j < 8; j++) acc[i][j] = 0.f;

    const int tm = (tid >> 4) * 8;
    const int tn = (tid & 15) * 8;

    {
        float4 a4 = *(const float4*)(Arow);
        float4 b4 = *(const float4*)(Brow);
        As[0][lk + 0][lm] = a4.x; As[0][lk + 1][lm] = a4.y;
        As[0][lk + 2][lm] = a4.z; As[0][lk + 3][lm] = a4.w;
        Bs[0][lk + 0][lm] = b4.x; Bs[0][lk + 1][lm] = b4.y;
        Bs[0][lk + 2][lm] = b4.z; Bs[0][lk + 3][lm] = b4.w;
    }
    __syncthreads();

    for (int t = 0; t < 128; t++) {
        const int cur = t & 1, nxt = cur ^ 1;
        float4 a4, b4;
        const bool more = (t + 1 < 128);
        if (more) {
            a4 = *(const float4*)(Arow + (t + 1) * 8);
            b4 = *(const float4*)(Brow + (t + 1) * 8);
        }
#pragma unroll
        for (int kk = 0; kk < 8; kk++) {
            float a[8], bb[8];
#pragma unroll
            for (int i = 0; i < 8; i++) a[i] = As[cur][kk][tm + i];
#pragma unroll
            for (int j = 0; j < 8; j++) bb[j] = Bs[cur][kk][tn + j];
#pragma unroll
            for (int i = 0; i < 8; i++)
#pragma unroll
                for (int j = 0; j < 8; j++) acc[i][j] += a[i] * bb[j];
        }
        if (more) {
            As[nxt][lk + 0][lm] = a4.x; As[nxt][lk + 1][lm] = a4.y;
            As[nxt][lk + 2][lm] = a4.z; As[nxt][lk + 3][lm] = a4.w;
            Bs[nxt][lk + 0][lm] = b4.x; Bs[nxt][lk + 1][lm] = b4.y;
            Bs[nxt][lk + 2][lm] = b4.z; Bs[nxt][lk + 3][lm] = b4.w;
        }
        __syncthreads();
    }

#pragma unroll
    for (int i = 0; i < 8; i++) {
        int m = bm * 128 + tm + i;
        float* crow = C + (size_t)m * 1024 + nbase + tn;
#pragma unroll
        for (int j = 0; j < 8; j++) crow[j] = acc[i][j];
    }
}

// ---------------------------------------------------------------------------
extern "C" void kernel_launch(void* const* d_in, const int* in_sizes, int n_in,
                              void* d_out, int out_size)
{
    const float* x      = (const float*)d_in[0];
    const float* Wq     = (const float*)d_in[1];
    const float* Wk     = (const float*)d_in[2];
    const float* Wv     = (const float*)d_in[3];
    const float* Wo     = (const float*)d_in[4];
    const float* Wg     = (const float*)d_in[5];
    const float* fw_W   = (const float*)d_in[6];
    const float* fw_b   = (const float*)d_in[7];
    const float* fw_g   = (const float*)d_in[8];
    const float* fw_bl  = (const float*)d_in[9];
    const float* ttt_g  = (const float*)d_in[10];
    const float* ttt_b  = (const float*)d_in[11];
    const float* post_g = (const float*)d_in[12];
    const float* post_b = (const float*)d_in[13];

    fused_kernel<<<16 + N_WORKERS, 256>>>(x, Wq, Wk, Wv, Wg,
                                          fw_W, fw_b, fw_g, fw_bl, ttt_g, ttt_b);
    post_kernel<<<B_ * S_, 256>>>(post_g, post_b);
    gemm2_kernel<<<dim3(8, 64), 256>>>(Wo, (float*)d_out);
}

// round 9
// speedup vs baseline: 3.7490x; 1.1180x over previous
#include <cuda_runtime.h>
#include <cstdint>

#define B_ 4
#define S_ 2048
#define E_ 1024
#define H_ 16
#define D_ 64
#define LN_EPS 1e-5f
#define LR 0.1f
#define INV64 0.015625f
#define C_GRAD (2.0f / 4096.0f)   // 2/(B*H*D)

#define N_WORKERS 296
#define NT_G1   2048              // qkvg projection tiles
#define NT_POST (NT_G1 + 64)      // post tiles (per chunk,b)
#define NT_ALL  (NT_POST + 512)   // output-projection tiles

// ---------------- scratch (device globals; no allocation allowed) ----------
__device__ float g_q[S_ * B_ * E_];
__device__ float g_k[S_ * B_ * E_];
__device__ float g_v[S_ * B_ * E_];
__device__ float g_gate[B_ * S_ * E_];
__device__ float g_scan[S_ * B_ * E_];
__device__ float g_y[B_ * S_ * E_];
__device__ int   g_ready[16];       // qkv tiles done per chunk (target 96)
__device__ int   g_gate_ready[16];  // gate tiles done per chunk (target 32)
__device__ int   g_scan_done[16];   // scan heads past chunk (target 16)
__device__ int   g_post_done[64];   // post tile done per (chunk*4+b)
__device__ int   g_tile;            // tile queue head
__device__ int   g_nscan;           // scan blocks that published smid
__device__ int   g_smids[16];

// ---------------------------------------------------------------------------
struct __align__(16) ScanSmem {
    float ks[2][B_][D_], ts[2][B_][D_], pt[2][B_][D_];
    float d1h[B_][D_], d1x[2][B_][D_], d1p[2][B_][D_];
    float d2h[B_][D_], d2x[B_][D_], d2p[B_][D_];
    float z2s[B_][D_], dsum[B_][D_];
    float Ms[B_][B_];
};
struct __align__(16) WorkSmem { float As[2][8][128]; float Bs[2][8][128]; };
union SmemU { ScanSmem sc; WorkSmem wk; };

// ---------------------------------------------------------------------------
__device__ __forceinline__ void bfly2(float& a, float& b)
{
#pragma unroll
    for (int o = 16; o > 0; o >>= 1) {
        a += __shfl_xor_sync(0xffffffffu, a, o);
        b += __shfl_xor_sync(0xffffffffu, b, o);
    }
}
__device__ __forceinline__ void bfly4(float& a, float& b, float& c, float& d)
{
#pragma unroll
    for (int o = 16; o > 0; o >>= 1) {
        a += __shfl_xor_sync(0xffffffffu, a, o);
        b += __shfl_xor_sync(0xffffffffu, b, o);
        c += __shfl_xor_sync(0xffffffffu, c, o);
        d += __shfl_xor_sync(0xffffffffu, d, o);
    }
}

__device__ __forceinline__ void wait_cnt(int* p, int target)
{
    if (*(volatile int*)p < target) {
        while (*(volatile int*)p < target) __nanosleep(256);
    }
    __threadfence();   // acquire
}

__device__ __forceinline__ unsigned my_smid()
{
    unsigned s;
    asm("mov.u32 %0, %%smid;" : "=r"(s));
    return s;
}

__device__ __forceinline__ float gelu_t(float x)
{
    float t = 0.7978845608028654f * (x + 0.044715f * x * x * x);
    return 0.5f * x * (1.0f + tanhf(t));
}

#define BAR_A()    asm volatile("bar.sync 1, 128;" ::: "memory")
#define BAR_B()    asm volatile("bar.sync 2, 128;" ::: "memory")
#define BAR_FULL() asm volatile("bar.sync 0, 256;" ::: "memory")

// ---------------------------------------------------------------------------
// Persistent worker loop over the unified tile queue:
//   [0, NT_G1):        qkvg projection gemm tiles (chunk-major, qkv first)
//   [NT_G1, NT_POST):  post-norm/gelu tiles (wait on scan+gate per chunk)
//   [NT_POST, NT_ALL): output-projection tiles (wait on post per (chunk,b))
// ---------------------------------------------------------------------------
__device__ void worker_loop(const float* __restrict__ x,
                            const float* __restrict__ Wq, const float* __restrict__ Wk,
                            const float* __restrict__ Wv, const float* __restrict__ Wg,
                            const float* __restrict__ Wo,
                            const float* __restrict__ post_g, const float* __restrict__ post_b,
                            float* __restrict__ C,
                            float (&As)[2][8][128], float (&Bs)[2][8][128],
                            int& s_tile)
{
    const int tid = threadIdx.x;
    const int lm = tid >> 1;
    const int lk = (tid & 1) * 4;
    const int tm = (tid >> 4) * 8;
    const int tn = (tid & 15) * 8;
    const int warp = tid >> 5;
    const int lane = tid & 31;

    for (;;) {
        if (tid == 0) s_tile = atomicAdd(&g_tile, 1);
        __syncthreads();
        const int gid = s_tile;
        if (gid >= NT_ALL) break;

        if (gid >= NT_G1 && gid < NT_POST) {
            // ---------------- post tile: 128 rows of one (chunk, b) ----------
            const int t = gid - NT_G1;
            const int chunk = t >> 2, b = t & 3;
            wait_cnt(&g_scan_done[chunk], 16);
            wait_cnt(&g_gate_ready[chunk], 32);

            for (int r = warp; r < 128; r += 8) {
                const int s = chunk * 128 + r;
                const float4* in = (const float4*)(g_scan + (size_t)(s * B_ + b) * E_);
                const float4* gp = (const float4*)(g_gate + (size_t)(b * 2048 + s) * E_);
                float4* out = (float4*)(g_y + (size_t)(b * 2048 + s) * E_);
                float4 v[8];
                float sum = 0.f, sq = 0.f;
#pragma unroll
                for (int i = 0; i < 8; i++) {
                    v[i] = in[lane + 32 * i];
                    sum += v[i].x + v[i].y + v[i].z + v[i].w;
                    sq  += v[i].x*v[i].x + v[i].y*v[i].y + v[i].z*v[i].z + v[i].w*v[i].w;
                }
                bfly2(sum, sq);
                float mu = sum * (1.0f / 1024.0f);
                float rs = rsqrtf(sq * (1.0f / 1024.0f) - mu * mu + LN_EPS);
#pragma unroll
                for (int i = 0; i < 8; i++) {
                    float4 pg = ((const float4*)post_g)[lane + 32 * i];
                    float4 pb = ((const float4*)post_b)[lane + 32 * i];
                    float4 gg = gp[lane + 32 * i];
                    float4 o;
                    o.x = gelu_t(gg.x) * ((v[i].x - mu) * rs * pg.x + pb.x);
                    o.y = gelu_t(gg.y) * ((v[i].y - mu) * rs * pg.y + pb.y);
                    o.z = gelu_t(gg.z) * ((v[i].z - mu) * rs * pg.z + pb.z);
                    o.w = gelu_t(gg.w) * ((v[i].w - mu) * rs * pg.w + pb.w);
                    out[lane + 32 * i] = o;
                }
            }
            __threadfence();
            __syncthreads();
            if (tid == 0) atomicAdd(&g_post_done[chunk * 4 + b], 1);
            continue;
        }

        // ---------------- gemm tile (projection or output) ----------------
        const float *Arow, *Brow;
        int chunk, b, bn, p, m0;
        if (gid < NT_G1) {
            int bmp;
            if (gid < 1536) { bmp = gid / 24; bn = gid % 24; }              // q,k,v
            else { int g2 = gid - 1536; bmp = g2 >> 3; bn = 24 + (g2 & 7); } // gate
            chunk = bmp >> 2; b = bmp & 3;
            m0 = b * 2048 + chunk * 128;
            const int nbase = bn * 128;
            p = nbase >> 10;
            const float* Bmat = (p == 0) ? Wq : (p == 1) ? Wk : (p == 2) ? Wv : Wg;
            Arow = x + (size_t)(m0 + lm) * 1024 + lk;
            Brow = Bmat + (size_t)((nbase & 1023) + lm) * 1024 + lk;
        } else {
            int g2 = gid - NT_POST;
            chunk = g2 >> 5;
            int rr = g2 & 31;
            b = rr >> 3; bn = rr & 7;
            p = 4;
            m0 = b * 2048 + chunk * 128;
            wait_cnt(&g_post_done[chunk * 4 + b], 1);
            Arow = g_y + (size_t)(m0 + lm) * 1024 + lk;
            Brow = Wo + (size_t)(bn * 128 + lm) * 1024 + lk;
        }

        float acc[8][8];
#pragma unroll
        for (int i = 0; i < 8; i++)
#pragma unroll
            for (int j = 0; j < 8; j++) acc[i][j] = 0.f;

        {
            float4 a4 = *(const float4*)(Arow);
            float4 b4 = *(const float4*)(Brow);
            As[0][lk + 0][lm] = a4.x; As[0][lk + 1][lm] = a4.y;
            As[0][lk + 2][lm] = a4.z; As[0][lk + 3][lm] = a4.w;
            Bs[0][lk + 0][lm] = b4.x; Bs[0][lk + 1][lm] = b4.y;
            Bs[0][lk + 2][lm] = b4.z; Bs[0][lk + 3][lm] = b4.w;
        }
        __syncthreads();

        for (int t = 0; t < 128; t++) {
            const int cur = t & 1, nxt = cur ^ 1;
            float4 a4, b4;
            const bool more = (t + 1 < 128);
            if (more) {
                a4 = *(const float4*)(Arow + (t + 1) * 8);
                b4 = *(const float4*)(Brow + (t + 1) * 8);
            }
#pragma unroll
            for (int kk = 0; kk < 8; kk++) {
                float a[8], bb[8];
#pragma unroll
                for (int i = 0; i < 8; i++) a[i] = As[cur][kk][tm + i];
#pragma unroll
                for (int j = 0; j < 8; j++) bb[j] = Bs[cur][kk][tn + j];
#pragma unroll
                for (int i = 0; i < 8; i++)
#pragma unroll
                    for (int j = 0; j < 8; j++) acc[i][j] += a[i] * bb[j];
            }
            if (more) {
                As[nxt][lk + 0][lm] = a4.x; As[nxt][lk + 1][lm] = a4.y;
                As[nxt][lk + 2][lm] = a4.z; As[nxt][lk + 3][lm] = a4.w;
                Bs[nxt][lk + 0][lm] = b4.x; Bs[nxt][lk + 1][lm] = b4.y;
                Bs[nxt][lk + 2][lm] = b4.z; Bs[nxt][lk + 3][lm] = b4.w;
            }
            __syncthreads();
        }

        if (p == 4) {
#pragma unroll
            for (int i = 0; i < 8; i++) {
                int m = m0 + tm + i;
                float* crow = C + (size_t)m * 1024 + bn * 128 + tn;
#pragma unroll
                for (int j = 0; j < 8; j++) crow[j] = acc[i][j];
            }
            __syncthreads();
        } else {
            const int f = ((bn * 128) & 1023) + tn;
#pragma unroll
            for (int i = 0; i < 8; i++) {
                int s = chunk * 128 + tm + i;
                if (p == 3) {
                    float* dst = g_gate + (size_t)(b * 2048 + s) * 1024 + f;
#pragma unroll
                    for (int j = 0; j < 8; j++) dst[j] = acc[i][j];
                } else {
                    float* dst = (p == 0 ? g_q : p == 1 ? g_k : g_v)
                                 + (size_t)(s * B_ + b) * 1024 + f;
#pragma unroll
                    for (int j = 0; j < 8; j++) dst[j] = acc[i][j];
                }
            }
            __threadfence();
            __syncthreads();
            if (tid == 0) {
                if (p < 3) atomicAdd(&g_ready[chunk], 1);
                else       atomicAdd(&g_gate_ready[chunk], 1);
            }
        }
    }
}

// ---------------------------------------------------------------------------
// Fused: blocks 0-15 = TTT scan (publish smid; join worker pool when done).
// Blocks 16.. = persistent workers; those landing on scan SMs exit.
// ---------------------------------------------------------------------------
__global__ void __launch_bounds__(256, 2)
fused_kernel(const float* __restrict__ x,
             const float* __restrict__ Wq, const float* __restrict__ Wk,
             const float* __restrict__ Wv, const float* __restrict__ Wg,
             const float* __restrict__ Wo,
             const float* __restrict__ fw_W, const float* __restrict__ fw_b,
             const float* __restrict__ fw_g, const float* __restrict__ fw_bl,
             const float* __restrict__ ttt_g, const float* __restrict__ ttt_b,
             const float* __restrict__ post_g, const float* __restrict__ post_b,
             float* __restrict__ C)
{
    __shared__ SmemU U;
    __shared__ int s_flag, s_tile;
    const int tid = threadIdx.x;

    if (blockIdx.x >= 16) {
        if (tid == 0) {
            unsigned smid = my_smid();
            int it = 0;
            while (*(volatile int*)&g_nscan < 16 && it < 50000) {
                __nanosleep(128); it++;
            }
            __threadfence();
            int excl = 0;
            if (*(volatile int*)&g_nscan >= 16) {
#pragma unroll
                for (int i = 0; i < 16; i++)
                    if (g_smids[i] == (int)smid) excl = 1;
            }
            s_flag = excl;
        }
        __syncthreads();
        if (s_flag) return;   // vacate scan SMs
        worker_loop(x, Wq, Wk, Wv, Wg, Wo, post_g, post_b, C,
                    U.wk.As, U.wk.Bs, s_tile);
        return;
    }

    // ==================== SCAN (blocks 0-15) ====================
    ScanSmem& SC = U.sc;
    const int h = blockIdx.x;
    const int l = tid & 31;
    const int hb = h * 64;

    if (tid == 0) {
        g_smids[h] = (int)my_smid();
        __threadfence();
        atomicAdd(&g_nscan, 1);
    }

    if (tid < 128) {
        // ================= GROUP A =================
        const int aw   = tid >> 5;
        const int ecol = tid & 63;
        const int rgrp = tid >> 6;
        const int lb   = tid >> 6;
        const int le   = tid & 63;

        float Wreg[32];
#pragma unroll
        for (int j = 0; j < 32; j++)
            Wreg[j] = fw_W[h * 4096 + (rgrp * 32 + j) * 64 + ecol];

        float bias0 = fw_b[hb + l],  bias1 = fw_b[hb + l + 32];
        float g0    = fw_g[hb + l],  g1    = fw_g[hb + l + 32];
        float bl0   = fw_bl[hb + l], bl1   = fw_bl[hb + l + 32];

        wait_cnt(&g_ready[0], 96);
        float kf0 = g_k[(size_t)lb * E_ + hb + le];
        float kf1 = g_k[(size_t)(lb + 2) * E_ + hb + le];
        float vf0 = g_v[(size_t)lb * E_ + hb + le];
        float vf1 = g_v[(size_t)(lb + 2) * E_ + hb + le];

        for (int s = 0; s < S_; s++) {
            const int par = s & 1;
            SC.ks[par][lb][le]     = kf0;
            SC.ks[par][lb + 2][le] = kf1;
            SC.ts[par][lb][le]     = vf0 - kf0;
            SC.ts[par][lb + 2][le] = vf1 - kf1;
            BAR_A();

            if (s + 1 < S_) {
                if (((s + 1) & 127) == 0) wait_cnt(&g_ready[(s + 1) >> 7], 96);
                size_t nb = (size_t)((s + 1) * B_ + lb) * E_ + hb + le;
                kf0 = g_k[nb]; kf1 = g_k[nb + 2 * E_];
                vf0 = g_v[nb]; vf1 = g_v[nb + 2 * E_];
            }

            // ---- matvec partials ----
            const float4* k40 = (const float4*)&SC.ks[par][0][rgrp * 32];
            const float4* k41 = (const float4*)&SC.ks[par][1][rgrp * 32];
            const float4* k42 = (const float4*)&SC.ks[par][2][rgrp * 32];
            const float4* k43 = (const float4*)&SC.ks[par][3][rgrp * 32];
            float a0 = 0.f, a1 = 0.f, a2 = 0.f, a3 = 0.f;
#pragma unroll
            for (int i = 0; i < 8; i++) {
                float4 c0 = k40[i], c1 = k41[i], c2 = k42[i], c3 = k43[i];
                float w0 = Wreg[4*i], w1 = Wreg[4*i+1], w2 = Wreg[4*i+2], w3 = Wreg[4*i+3];
                a0 += c0.x*w0 + c0.y*w1 + c0.z*w2 + c0.w*w3;
                a1 += c1.x*w0 + c1.y*w1 + c1.z*w2 + c1.w*w3;
                a2 += c2.x*w0 + c2.y*w1 + c2.z*w2 + c2.w*w3;
                a3 += c3.x*w0 + c3.y*w1 + c3.z*w2 + c3.w*w3;
            }
            SC.pt[rgrp][0][ecol] = a0;
            SC.pt[rgrp][1][ecol] = a1;
            SC.pt[rgrp][2][ecol] = a2;
            SC.pt[rgrp][3][ecol] = a3;
            BAR_A();

            // ---- combine + LN1 ----
            float z0 = bias0 + SC.pt[0][aw][l]      + SC.pt[1][aw][l];
            float z1 = bias1 + SC.pt[0][aw][l + 32] + SC.pt[1][aw][l + 32];
            float sum = z0 + z1, sq = z0 * z0 + z1 * z1;
            bfly2(sum, sq);
            float mu   = sum * INV64;
            float rstd = rsqrtf(sq * INV64 - mu * mu + LN_EPS);
            float xh0 = (z0 - mu) * rstd, xh1 = (z1 - mu) * rstd;

            // ---- bwd1 ----
            float t0 = SC.ts[par][aw][l], t1 = SC.ts[par][aw][l + 32];
            float p0 = xh0 * g0 + bl0, p1 = xh1 * g1 + bl1;
            float dp0 = C_GRAD * (p0 - t0), dp1 = C_GRAD * (p1 - t1);
            float dx0 = dp0 * g0, dx1 = dp1 * g1;
            float S1 = dx0 + dx1, S2 = dx0 * xh0 + dx1 * xh1;
            bfly2(S1, S2);
            float dh0 = rstd * (dx0 - (S1 + xh0 * S2) * INV64);
            float dh1 = rstd * (dx1 - (S1 + xh1 * S2) * INV64);
            SC.d1h[aw][l]          = dh0;
            SC.d1h[aw][l + 32]     = dh1;
            SC.d1x[par][aw][l]      = dp0 * xh0;
            SC.d1x[par][aw][l + 32] = dp1 * xh1;
            SC.d1p[par][aw][l]      = dp0;
            SC.d1p[par][aw][l + 32] = dp1;
            BAR_FULL();                                   // A3

            // ---- param update 1 ----
            float sx0 = SC.d1x[par][0][l] + SC.d1x[par][1][l] + SC.d1x[par][2][l] + SC.d1x[par][3][l];
            float sx1 = SC.d1x[par][0][l+32] + SC.d1x[par][1][l+32] + SC.d1x[par][2][l+32] + SC.d1x[par][3][l+32];
            float sp0 = SC.d1p[par][0][l] + SC.d1p[par][1][l] + SC.d1p[par][2][l] + SC.d1p[par][3][l];
            float sp1 = SC.d1p[par][0][l+32] + SC.d1p[par][1][l+32] + SC.d1p[par][2][l+32] + SC.d1p[par][3][l+32];
            g0 -= LR * sx0; g1 -= LR * sx1;
            bl0 -= LR * sp0; bl1 -= LR * sp1;

            // ---- corr2 ----
            float m0 = SC.Ms[aw][0], m1 = SC.Ms[aw][1], m2 = SC.Ms[aw][2], m3 = SC.Ms[aw][3];
            z0 += m0 * SC.d1h[0][l] + m1 * SC.d1h[1][l] + m2 * SC.d1h[2][l] + m3 * SC.d1h[3][l];
            z1 += m0 * SC.d1h[0][l+32] + m1 * SC.d1h[1][l+32] + m2 * SC.d1h[2][l+32] + m3 * SC.d1h[3][l+32];

            // ---- LN2 ----
            sum = z0 + z1; sq = z0 * z0 + z1 * z1;
            bfly2(sum, sq);
            mu   = sum * INV64;
            rstd = rsqrtf(sq * INV64 - mu * mu + LN_EPS);
            xh0 = (z0 - mu) * rstd; xh1 = (z1 - mu) * rstd;

            // ---- bwd2 ----
            p0 = xh0 * g0 + bl0; p1 = xh1 * g1 + bl1;
            dp0 = C_GRAD * (p0 - t0); dp1 = C_GRAD * (p1 - t1);
            dx0 = dp0 * g0; dx1 = dp1 * g1;
            S1 = dx0 + dx1; S2 = dx0 * xh0 + dx1 * xh1;
            bfly2(S1, S2);
            float e0 = rstd * (dx0 - (S1 + xh0 * S2) * INV64);
            float e1 = rstd * (dx1 - (S1 + xh1 * S2) * INV64);

            // ---- share2 ----
            SC.z2s[aw][l]       = z0;   SC.z2s[aw][l + 32]  = z1;
            SC.d2h[aw][l]       = e0;   SC.d2h[aw][l + 32]  = e1;
            SC.d2x[aw][l]       = dp0 * xh0; SC.d2x[aw][l + 32] = dp1 * xh1;
            SC.d2p[aw][l]       = dp0;  SC.d2p[aw][l + 32]  = dp1;
            SC.dsum[aw][l]      = dh0 + e0;
            SC.dsum[aw][l + 32] = dh1 + e1;
            BAR_FULL();                                   // S3

            // ---- param update 2 ----
            sx0 = SC.d2x[0][l] + SC.d2x[1][l] + SC.d2x[2][l] + SC.d2x[3][l];
            sx1 = SC.d2x[0][l+32] + SC.d2x[1][l+32] + SC.d2x[2][l+32] + SC.d2x[3][l+32];
            sp0 = SC.d2p[0][l] + SC.d2p[1][l] + SC.d2p[2][l] + SC.d2p[3][l];
            sp1 = SC.d2p[0][l+32] + SC.d2p[1][l+32] + SC.d2p[2][l+32] + SC.d2p[3][l+32];
            g0 -= LR * sx0; g1 -= LR * sx1;
            bl0 -= LR * sp0; bl1 -= LR * sp1;
            bias0 -= LR * (SC.dsum[0][l] + SC.dsum[1][l] + SC.dsum[2][l] + SC.dsum[3][l]);
            bias1 -= LR * (SC.dsum[0][l+32] + SC.dsum[1][l+32] + SC.dsum[2][l+32] + SC.dsum[3][l+32]);

            // ---- W update ----
            float ds0 = LR * SC.dsum[0][ecol];
            float ds1 = LR * SC.dsum[1][ecol];
            float ds2 = LR * SC.dsum[2][ecol];
            float ds3 = LR * SC.dsum[3][ecol];
#pragma unroll
            for (int i = 0; i < 8; i++) {
                float4 c0 = k40[i], c1 = k41[i], c2 = k42[i], c3 = k43[i];
                Wreg[4*i]   -= c0.x*ds0 + c1.x*ds1 + c2.x*ds2 + c3.x*ds3;
                Wreg[4*i+1] -= c0.y*ds0 + c1.y*ds1 + c2.y*ds2 + c3.y*ds3;
                Wreg[4*i+2] -= c0.z*ds0 + c1.z*ds1 + c2.z*ds2 + c3.z*ds3;
                Wreg[4*i+3] -= c0.w*ds0 + c1.w*ds1 + c2.w*ds2 + c3.w*ds3;
            }
        }
    } else {
        // ================= GROUP B =================
        const int bw = (tid >> 5) - 4;

        float g0  = fw_g[hb + l],  g1  = fw_g[hb + l + 32];
        float bl0 = fw_bl[hb + l], bl1 = fw_bl[hb + l + 32];
        float tg0 = ttt_g[hb + l], tg1 = ttt_g[hb + l + 32];
        float tb0 = ttt_b[hb + l], tb1 = ttt_b[hb + l + 32];

        wait_cnt(&g_ready[0], 96);
        float kk0[4], kk1[4];
#pragma unroll
        for (int b = 0; b < 4; b++) {
            kk0[b] = g_k[(size_t)b * E_ + hb + l];
            kk1[b] = g_k[(size_t)b * E_ + hb + l + 32];
        }
        float Mreg[4];
        {
            float P0 = kk0[bw]*kk0[0] + kk1[bw]*kk1[0];
            float P1 = kk0[bw]*kk0[1] + kk1[bw]*kk1[1];
            float P2 = kk0[bw]*kk0[2] + kk1[bw]*kk1[2];
            float P3 = kk0[bw]*kk0[3] + kk1[bw]*kk1[3];
            bfly4(P0, P1, P2, P3);
            Mreg[0] = -LR * (P0 + 1.0f);
            Mreg[1] = -LR * (P1 + 1.0f);
            Mreg[2] = -LR * (P2 + 1.0f);
            Mreg[3] = -LR * (P3 + 1.0f);
            if (l == 0) {
                SC.Ms[bw][0] = Mreg[0]; SC.Ms[bw][1] = Mreg[1];
                SC.Ms[bw][2] = Mreg[2]; SC.Ms[bw][3] = Mreg[3];
            }
        }
        float q0 = g_q[(size_t)bw * E_ + hb + l];
        float q1 = g_q[(size_t)bw * E_ + hb + l + 32];
#pragma unroll
        for (int b = 0; b < 4; b++) {
            kk0[b] = g_k[(size_t)(1 * B_ + b) * E_ + hb + l];
            kk1[b] = g_k[(size_t)(1 * B_ + b) * E_ + hb + l + 32];
        }

        for (int s = 0; s < S_; s++) {
            BAR_FULL();                                   // A3
            BAR_FULL();                                   // S3
            const int par = s & 1;

            // ---- combined param update ----
            float sx0 = 0.f, sx1 = 0.f, sp0 = 0.f, sp1 = 0.f;
#pragma unroll
            for (int b = 0; b < 4; b++) {
                sx0 += SC.d1x[par][b][l]      + SC.d2x[b][l];
                sx1 += SC.d1x[par][b][l + 32] + SC.d2x[b][l + 32];
                sp0 += SC.d1p[par][b][l]      + SC.d2p[b][l];
                sp1 += SC.d1p[par][b][l + 32] + SC.d2p[b][l + 32];
            }
            g0 -= LR * sx0; g1 -= LR * sx1;
            bl0 -= LR * sp0; bl1 -= LR * sp1;

            // ---- corr3 ----
            float z0 = SC.z2s[bw][l]
                     + Mreg[0]*SC.d2h[0][l] + Mreg[1]*SC.d2h[1][l]
                     + Mreg[2]*SC.d2h[2][l] + Mreg[3]*SC.d2h[3][l];
            float z1 = SC.z2s[bw][l + 32]
                     + Mreg[0]*SC.d2h[0][l+32] + Mreg[1]*SC.d2h[1][l+32]
                     + Mreg[2]*SC.d2h[2][l+32] + Mreg[3]*SC.d2h[3][l+32];

            // ---- LN3 ----
            float sum = z0 + z1, sq = z0 * z0 + z1 * z1;
            bfly2(sum, sq);
            float mu = sum * INV64;
            float rs = rsqrtf(sq * INV64 - mu * mu + LN_EPS);
            float p0 = (z0 - mu) * rs * g0 + bl0;
            float p1 = (z1 - mu) * rs * g1 + bl1;

            // ---- LN4 + add q + store ----
            sum = p0 + p1; sq = p0 * p0 + p1 * p1;
            bfly2(sum, sq);
            mu = sum * INV64;
            rs = rsqrtf(sq * INV64 - mu * mu + LN_EPS);
            size_t ob = (size_t)(s * B_ + bw) * E_ + hb + l;
            g_scan[ob]      = q0 + (p0 - mu) * rs * tg0 + tb0;
            g_scan[ob + 32] = q1 + (p1 - mu) * rs * tg1 + tb1;

            // ---- chunk-complete signal for the post/gemm2 pipeline ----
            if ((s & 127) == 127) {
                __threadfence();
                BAR_B();
                if (tid == 128) atomicAdd(&g_scan_done[s >> 7], 1);
            }

            if (s + 1 < S_) {
                float P0 = kk0[bw]*kk0[0] + kk1[bw]*kk1[0];
                float P1 = kk0[bw]*kk0[1] + kk1[bw]*kk1[1];
                float P2 = kk0[bw]*kk0[2] + kk1[bw]*kk1[2];
                float P3 = kk0[bw]*kk0[3] + kk1[bw]*kk1[3];
                bfly4(P0, P1, P2, P3);
                Mreg[0] = -LR * (P0 + 1.0f);
                Mreg[1] = -LR * (P1 + 1.0f);
                Mreg[2] = -LR * (P2 + 1.0f);
                Mreg[3] = -LR * (P3 + 1.0f);
                if (l == 0) {
                    SC.Ms[bw][0] = Mreg[0]; SC.Ms[bw][1] = Mreg[1];
                    SC.Ms[bw][2] = Mreg[2]; SC.Ms[bw][3] = Mreg[3];
                }
                size_t qb = (size_t)((s + 1) * B_ + bw) * E_ + hb + l;
                q0 = g_q[qb];
                q1 = g_q[qb + 32];
                if (s + 2 < S_) {
                    if (((s + 2) & 127) == 0) wait_cnt(&g_ready[(s + 2) >> 7], 96);
#pragma unroll
                    for (int b = 0; b < 4; b++) {
                        size_t kb = (size_t)((s + 2) * B_ + b) * E_ + hb + l;
                        kk0[b] = g_k[kb];
                        kk1[b] = g_k[kb + 32];
                    }
                }
            }
        }
    }

    // scan finished: this block's SM is free — join the worker pool
    worker_loop(x, Wq, Wk, Wv, Wg, Wo, post_g, post_b, C,
                U.wk.As, U.wk.Bs, s_tile);
}

// ---------------------------------------------------------------------------
// Reset queue/flag globals for the next graph replay (runs after fused).
// ---------------------------------------------------------------------------
__global__ void reset_kernel()
{
    const int t = threadIdx.x;
    if (t < 16) { g_ready[t] = 0; g_gate_ready[t] = 0; g_scan_done[t] = 0; }
    if (t < 64) g_post_done[t] = 0;
    if (t == 64) { g_tile = 0; g_nscan = 0; }
}

// ---------------------------------------------------------------------------
extern "C" void kernel_launch(void* const* d_in, const int* in_sizes, int n_in,
                              void* d_out, int out_size)
{
    const float* x      = (const float*)d_in[0];
    const float* Wq     = (const float*)d_in[1];
    const float* Wk     = (const float*)d_in[2];
    const float* Wv     = (const float*)d_in[3];
    const float* Wo     = (const float*)d_in[4];
    const float* Wg     = (const float*)d_in[5];
    const float* fw_W   = (const float*)d_in[6];
    const float* fw_b   = (const float*)d_in[7];
    const float* fw_g   = (const float*)d_in[8];
    const float* fw_bl  = (const float*)d_in[9];
    const float* ttt_g  = (const float*)d_in[10];
    const float* ttt_b  = (const float*)d_in[11];
    const float* post_g = (const float*)d_in[12];
    const float* post_b = (const float*)d_in[13];

    fused_kernel<<<16 + N_WORKERS, 256>>>(x, Wq, Wk, Wv, Wg, Wo,
                                          fw_W, fw_b, fw_g, fw_bl,
                                          ttt_g, ttt_b, post_g, post_b,
                                          (float*)d_out);
    reset_kernel<<<1, 128>>>();
}